// round 13
// baseline (speedup 1.0000x reference)
#include <cuda_runtime.h>
#include <cuda_bf16.h>
#include <cuda_fp16.h>
#include <stdint.h>
#include <math.h>

#define B_    4
#define NSEQ  4096
#define MTOT  (B_*NSEQ)
#define D_    256
#define NOUT  128
#define EPS   1e-5f
#define EROWS 16

typedef __nv_bfloat16 bf16;

// ---- scratch (static device globals; no allocation allowed) ----
__device__ float  g_Q [(size_t)MTOT*D_];
__device__ float  g_Qh[(size_t)MTOT*D_];
__device__ __half g_Qhi16[(size_t)MTOT*D_], g_Qlo16[(size_t)MTOT*D_];
__device__ __half g_K16  [(size_t)MTOT*D_];
__device__ bf16   g_tQhi[(size_t)MTOT*D_], g_tQlo[(size_t)MTOT*D_];
__device__ bf16   g_tKhi[(size_t)MTOT*D_], g_tKlo[(size_t)MTOT*D_];
__device__ __half g_Vt16[(size_t)MTOT*D_];                           // [B][D][NSEQ]
__device__ __half g_Phi16[(size_t)B_*NSEQ*NSEQ], g_Plo16[(size_t)B_*NSEQ*NSEQ];
// fp16 hi/lo of inputs + transposed weights
__device__ __half g_x1h[(size_t)MTOT*D_], g_x1l[(size_t)MTOT*D_];
__device__ __half g_x2h[(size_t)MTOT*D_], g_x2l[(size_t)MTOT*D_];
__device__ __half g_wqh[D_*D_], g_wql[D_*D_];
__device__ __half g_wkh[D_*D_], g_wkl[D_*D_];
__device__ __half g_wvh[D_*D_], g_wvl[D_*D_];

__device__ __forceinline__ void split_bf16(float x, bf16& h, bf16& l) {
    h = __float2bfloat16(x);
    l = __float2bfloat16(x - __bfloat162float(h));
}
__device__ __forceinline__ void split_f16(float x, __half& h, __half& l) {
    h = __float2half_rn(x);
    l = __float2half_rn(x - __half2float(h));
}

__device__ __forceinline__ uint32_t smem_u32(const void* p) {
    uint32_t a;
    asm("{ .reg .u64 t; cvta.to.shared.u64 t, %1; cvt.u32.u64 %0, t; }" : "=r"(a) : "l"(p));
    return a;
}

#define CP_ASYNC16(dst, src) \
    asm volatile("cp.async.cg.shared.global [%0], [%1], 16;" :: "r"(dst), "l"(src) : "memory")
#define CP_COMMIT() asm volatile("cp.async.commit_group;" ::: "memory")
#define CP_WAIT1()  asm volatile("cp.async.wait_group 1;" ::: "memory")

// bf16 m16n8k16 mma, fp32 accum
__device__ __forceinline__ void mma16816(float* d, const unsigned* a, const unsigned* b) {
    asm volatile(
        "mma.sync.aligned.m16n8k16.row.col.f32.bf16.bf16.f32 "
        "{%0,%1,%2,%3}, {%4,%5,%6,%7}, {%8,%9}, {%0,%1,%2,%3};\n"
        : "+f"(d[0]), "+f"(d[1]), "+f"(d[2]), "+f"(d[3])
        : "r"(a[0]), "r"(a[1]), "r"(a[2]), "r"(a[3]), "r"(b[0]), "r"(b[1]));
}
// fp16 m16n8k16 mma, fp32 accum
__device__ __forceinline__ void mma16816h(float* d, const unsigned* a, const unsigned* b) {
    asm volatile(
        "mma.sync.aligned.m16n8k16.row.col.f32.f16.f16.f32 "
        "{%0,%1,%2,%3}, {%4,%5,%6,%7}, {%8,%9}, {%0,%1,%2,%3};\n"
        : "+f"(d[0]), "+f"(d[1]), "+f"(d[2]), "+f"(d[3])
        : "r"(a[0]), "r"(a[1]), "r"(a[2]), "r"(a[3]), "r"(b[0]), "r"(b[1]));
}

__device__ __forceinline__ void ldsm_x4(uint32_t addr, unsigned* r) {
    asm volatile("ldmatrix.sync.aligned.m8n8.x4.shared.b16 {%0,%1,%2,%3}, [%4];"
        : "=r"(r[0]), "=r"(r[1]), "=r"(r[2]), "=r"(r[3]) : "r"(addr));
}

// ================= converts =================================================
__global__ __launch_bounds__(256) void convert_x_kernel(
    const float* __restrict__ x, __half* __restrict__ xh, __half* __restrict__ xl)
{
    int i = blockIdx.x*256 + threadIdx.x;          // over float4 units
    float4 v = ((const float4*)x)[i];
    __half h[4], l[4];
    split_f16(v.x,h[0],l[0]); split_f16(v.y,h[1],l[1]);
    split_f16(v.z,h[2],l[2]); split_f16(v.w,h[3],l[3]);
    __half2 h01; h01.x=h[0]; h01.y=h[1];
    __half2 h23; h23.x=h[2]; h23.y=h[3];
    __half2 l01; l01.x=l[0]; l01.y=l[1];
    __half2 l23; l23.x=l[2]; l23.y=l[3];
    ((__half2*)xh)[i*2]=h01; ((__half2*)xh)[i*2+1]=h23;
    ((__half2*)xl)[i*2]=l01; ((__half2*)xl)[i*2+1]=l23;
}

// W [K=256][N=256] -> Wt hi/lo [N][K]
__global__ __launch_bounds__(256) void convert_wt_kernel(
    const float* __restrict__ W, __half* __restrict__ Wth, __half* __restrict__ Wtl)
{
    int n = blockIdx.x, k = threadIdx.x;
    float v = W[k*D_ + n];
    __half h,l; split_f16(v,h,l);
    Wth[n*D_ + k]=h; Wtl[n*D_ + k]=l;
}

// ================= tensor-core projection ==================================
// A: X hi/lo [128 rows]; B: Wt hi/lo [256 rows]; stage = 2*5120 + 2*10240 =
// 30720 el = 61440 B; 3 stages.  MODE 0=Q, 1=K, 2=V(transposed out)
#define PJ_STAGE_B 61440

__device__ __forceinline__ void pj_load_chunk(
    const __half* const* Am, const __half* const* Bm, uint32_t stage_b, int kc, int tid)
{
    #pragma unroll
    for (int t=0;t<6;t++) {
        int i = tid + t*512;                   // 0..3071
        const __half* src; uint32_t dst;
        if (i < 1024) {
            int m = i >> 9, rem = i & 511, row = rem >> 2, c8 = rem & 3;
            src = Am[m] + (size_t)row*D_ + kc + c8*8;
            dst = stage_b + (uint32_t)(m*5120 + row*40 + c8*8)*2u;
        } else {
            int j = i - 1024;                  // 0..2047
            int m = j >> 10, rem = j & 1023, row = rem >> 2, c8 = rem & 3;
            src = Bm[m] + (size_t)row*D_ + kc + c8*8;
            dst = stage_b + (uint32_t)(10240 + m*10240 + row*40 + c8*8)*2u;
        }
        CP_ASYNC16(dst, src);
    }
}

template<int MODE>
__global__ __launch_bounds__(512,1) void proj_mma_kernel(
    const __half* __restrict__ Xh, const __half* __restrict__ Xl,
    const __half* __restrict__ Wth, const __half* __restrict__ Wtl,
    const float* __restrict__ bias,
    float* __restrict__ Qf,
    __half* __restrict__ O1, __half* __restrict__ O2,
    bf16* __restrict__ O3, bf16* __restrict__ O4)
{
    extern __shared__ __align__(16) bf16 sm[];
    const uint32_t smb = smem_u32(sm);
    const int tid = threadIdx.x;
    const int warp = tid >> 5, lane = tid & 31;
    const int wm = warp >> 3, wn = warp & 7;      // 2 x 8
    const int g = lane >> 2, t4 = lane & 3;
    const int m3 = lane >> 3, rr = lane & 7;
    const int aRowOff = ((m3 & 1) << 3) + rr, aColOff = (m3 >> 1) << 3;
    const int bRowOff = ((m3 >> 1) << 3) + rr, bColOff = (m3 & 1) << 3;
    const int q0 = blockIdx.x * 128;

    const __half* Am[2] = { Xh + (size_t)q0*D_, Xl + (size_t)q0*D_ };
    const __half* Bm[2] = { Wth, Wtl };

    float acc[4][4][4] = {};

    pj_load_chunk(Am, Bm, smb, 0, tid);  CP_COMMIT();
    pj_load_chunk(Am, Bm, smb + PJ_STAGE_B, 32, tid);  CP_COMMIT();

    for (int ch = 0; ch < 8; ch++) {
        uint32_t sbase = smb + (uint32_t)(ch % 3) * PJ_STAGE_B;
        CP_WAIT1();
        __syncthreads();
        if (ch + 2 < 8)
            pj_load_chunk(Am, Bm, smb + (uint32_t)((ch+2) % 3) * PJ_STAGE_B, (ch+2)*32, tid);
        CP_COMMIT();
        #pragma unroll
        for (int ks = 0; ks < 2; ks++) {
            const int kb0 = ks*16;
            unsigned bF[2][4][2];
            #pragma unroll
            for (int mat = 0; mat < 2; mat++)
                #pragma unroll
                for (int p = 0; p < 2; p++) {
                    int N0 = wn*32 + p*16;
                    uint32_t addr = sbase + (uint32_t)(10240 + mat*10240 + (N0 + bRowOff)*40 + kb0 + bColOff)*2u;
                    unsigned r[4]; ldsm_x4(addr, r);
                    bF[mat][2*p  ][0]=r[0]; bF[mat][2*p  ][1]=r[1];
                    bF[mat][2*p+1][0]=r[2]; bF[mat][2*p+1][1]=r[3];
                }
            #pragma unroll
            for (int mt = 0; mt < 4; mt++) {
                int R = wm*64 + mt*16;
                unsigned a0[4], a1[4];
                uint32_t abase = sbase + (uint32_t)((R + aRowOff)*40 + kb0 + aColOff)*2u;
                ldsm_x4(abase,          a0);   // Xhi
                ldsm_x4(abase + 10240u, a1);   // Xlo
                #pragma unroll
                for (int nt=0; nt<4; nt++) {
                    mma16816h(acc[mt][nt], a0, bF[0][nt]);
                    mma16816h(acc[mt][nt], a0, bF[1][nt]);
                    mma16816h(acc[mt][nt], a1, bF[0][nt]);
                }
            }
        }
    }

    if (MODE == 2) {
        // transpose through smem for coalesced Vt writes
        __half* Vs = (__half*)sm;              // [256 cols][136 rows pad]
        __syncthreads();
        #pragma unroll
        for (int mt=0; mt<4; mt++)
            #pragma unroll
            for (int nt=0; nt<4; nt++) {
                int rl = wm*64 + mt*16 + g;
                int c  = wn*32 + nt*8 + 2*t4;
                float b0 = bias[c], b1 = bias[c+1];
                Vs[(c  )*136 + rl    ] = __float2half_rn(acc[mt][nt][0] + b0);
                Vs[(c+1)*136 + rl    ] = __float2half_rn(acc[mt][nt][1] + b1);
                Vs[(c  )*136 + rl + 8] = __float2half_rn(acc[mt][nt][2] + b0);
                Vs[(c+1)*136 + rl + 8] = __float2half_rn(acc[mt][nt][3] + b1);
            }
        __syncthreads();
        int b = q0 >> 12, s0 = q0 & 4095;
        for (int i = tid; i < 256*16; i += 512) {
            int c = i >> 4, seg = i & 15;
            uint4 v = *(uint4*)(Vs + c*136 + seg*8);
            *(uint4*)(O1 + ((size_t)b*D_ + c)*NSEQ + s0 + seg*8) = v;
        }
    } else {
        #pragma unroll
        for (int mt=0; mt<4; mt++)
            #pragma unroll
            for (int nt=0; nt<4; nt++) {
                size_t r = q0 + wm*64 + mt*16 + g;
                int c = wn*32 + nt*8 + 2*t4;
                float b0 = bias[c], b1 = bias[c+1];
                float v[4] = { acc[mt][nt][0] + b0, acc[mt][nt][1] + b1,
                               acc[mt][nt][2] + b0, acc[mt][nt][3] + b1 };
                size_t idx[4] = { r*D_+c, r*D_+c+1, (r+8)*D_+c, (r+8)*D_+c+1 };
                #pragma unroll
                for (int u=0; u<4; u++) {
                    if (MODE == 0) {
                        Qf[idx[u]] = v[u];
                        __half hh,hl; split_f16(v[u], hh, hl);
                        O1[idx[u]]=hh; O2[idx[u]]=hl;
                        float t = tanhf(v[u]);
                        bf16 h,l; split_bf16(t, h, l);
                        O3[idx[u]]=h; O4[idx[u]]=l;
                    } else {
                        O1[idx[u]] = __float2half_rn(v[u]);
                        float t = tanhf(v[u]);
                        bf16 h,l; split_bf16(t, h, l);
                        O3[idx[u]]=h; O4[idx[u]]=l;
                    }
                }
            }
    }
}

// ====== dual-GEMM scores: 7 mats, fp16-asym QK + bf16 3-term tanh ==========
#define SC_STAGE_EL 35840
#define SC_STAGE_B  71680

__device__ __forceinline__ void sc_load_chunk(
    const bf16* const* P, uint32_t stage_b, int kc, int tid)
{
    #pragma unroll
    for (int t=0;t<7;t++) {
        int i = tid + t*512;                    // 0..3583
        int m = i >> 9, rem = i & 511, row = rem >> 2, c8 = rem & 3;
        const bf16* src = P[m] + (size_t)row*D_ + kc + c8*8;
        uint32_t dst = stage_b + (uint32_t)(m*5120 + row*40 + c8*8)*2u;
        CP_ASYNC16(dst, src);
    }
}

__global__ __launch_bounds__(512,1) void scores_mma_kernel(
    const __half* __restrict__ Qhi16, const __half* __restrict__ Qlo16,
    const bf16* __restrict__ tQhi, const bf16* __restrict__ tQlo,
    const __half* __restrict__ K16,
    const bf16* __restrict__ tKhi, const bf16* __restrict__ tKlo,
    float* __restrict__ attn)
{
    extern __shared__ __align__(16) bf16 sm[];
    const uint32_t smb = smem_u32(sm);
    const int tid = threadIdx.x;
    const int warp = tid >> 5, lane = tid & 31;
    const int wm = warp >> 2, wn = warp & 3;
    const int g = lane >> 2, t4 = lane & 3;
    const int m3 = lane >> 3, rr = lane & 7;
    const int aRowOff = ((m3 & 1) << 3) + rr, aColOff = (m3 >> 1) << 3;
    const int bRowOff = ((m3 >> 1) << 3) + rr, bColOff = (m3 & 1) << 3;
    const int bz = blockIdx.z;
    const int q0 = blockIdx.y * 128, c0 = blockIdx.x * 128;

    const bf16* P[7] = {
        (const bf16*)(Qhi16 + ((size_t)bz*NSEQ + q0)*D_),
        (const bf16*)(Qlo16 + ((size_t)bz*NSEQ + q0)*D_),
        tQhi + ((size_t)bz*NSEQ + q0)*D_,
        tQlo + ((size_t)bz*NSEQ + q0)*D_,
        (const bf16*)(K16 + ((size_t)bz*NSEQ + c0)*D_),
        tKhi + ((size_t)bz*NSEQ + c0)*D_,
        tKlo + ((size_t)bz*NSEQ + c0)*D_ };

    float accQ[2][4][4] = {};
    float accT[2][4][4] = {};

    sc_load_chunk(P, smb, 0, tid);  CP_COMMIT();
    sc_load_chunk(P, smb + SC_STAGE_B, 32, tid);  CP_COMMIT();

    for (int ch = 0; ch < 8; ch++) {
        uint32_t sbase = smb + (uint32_t)(ch % 3) * SC_STAGE_B;
        CP_WAIT1();
        __syncthreads();
        if (ch + 2 < 8)
            sc_load_chunk(P, smb + (uint32_t)((ch+2) % 3) * SC_STAGE_B, (ch+2)*32, tid);
        CP_COMMIT();
        #pragma unroll
        for (int ks = 0; ks < 2; ks++) {
            const int kb0 = ks*16;
            unsigned bF[3][4][2];
            #pragma unroll
            for (int mb = 0; mb < 3; mb++)
                #pragma unroll
                for (int p = 0; p < 2; p++) {
                    int N0 = wn*32 + p*16;
                    uint32_t addr = sbase + (uint32_t)((4+mb)*5120 + (N0 + bRowOff)*40 + kb0 + bColOff)*2u;
                    unsigned r[4]; ldsm_x4(addr, r);
                    bF[mb][2*p  ][0]=r[0]; bF[mb][2*p  ][1]=r[1];
                    bF[mb][2*p+1][0]=r[2]; bF[mb][2*p+1][1]=r[3];
                }
            #pragma unroll
            for (int mt = 0; mt < 2; mt++) {
                int R = wm*32 + mt*16;
                unsigned a0[4], a1[4], a2[4], a3[4];
                uint32_t abase = sbase + (uint32_t)((R + aRowOff)*40 + kb0 + aColOff)*2u;
                ldsm_x4(abase,            a0);   // Qhi16
                ldsm_x4(abase + 10240u,   a1);   // Qlo16
                ldsm_x4(abase + 20480u,   a2);   // tQhi
                ldsm_x4(abase + 30720u,   a3);   // tQlo
                #pragma unroll
                for (int nt=0; nt<4; nt++) {
                    mma16816h(accQ[mt][nt], a0, bF[0][nt]);
                    mma16816h(accQ[mt][nt], a1, bF[0][nt]);
                    mma16816 (accT[mt][nt], a2, bF[1][nt]);
                    mma16816 (accT[mt][nt], a2, bF[2][nt]);
                    mma16816 (accT[mt][nt], a3, bF[1][nt]);
                }
            }
        }
    }

    float* ob = attn + (size_t)bz*NSEQ*NSEQ;
    #pragma unroll
    for (int mt=0; mt<2; mt++)
        #pragma unroll
        for (int nt=0; nt<4; nt++) {
            int r = q0 + wm*32 + mt*16 + g;
            int c = c0 + wn*32 + nt*8 + 2*t4;
            const float* aq = accQ[mt][nt];
            const float* at = accT[mt][nt];
            float2 v0 = { aq[0]*(at[0]+1.0f)*0.03125f, aq[1]*(at[1]+1.0f)*0.03125f };
            float2 v1 = { aq[2]*(at[2]+1.0f)*0.03125f, aq[3]*(at[3]+1.0f)*0.03125f };
            *(float2*)(ob + (size_t)r*NSEQ + c)     = v0;
            *(float2*)(ob + (size_t)(r+8)*NSEQ + c) = v1;
        }
}

// ========= Qhat = attn @ V — fp16 asym: P hi/lo fp16 × V fp16 ===============
#define AV_STAGE_EL 20480
#define AV_STAGE_B  40960
#define AV_NCHUNK  (NSEQ/32)

__device__ __forceinline__ void av_load_chunk(
    const __half* const* Am, const __half* Bm, uint32_t stage_b, int kc, int tid)
{
    #pragma unroll
    for (int t=0;t<4;t++) {
        int i = tid + t*512;                   // 0..2047
        const __half* src; uint32_t dst;
        if (i < 1024) {
            int m = i >> 9, rem = i & 511, row = rem >> 2, c8 = rem & 3;
            src = Am[m] + (size_t)row*NSEQ + kc + c8*8;
            dst = stage_b + (uint32_t)(m*5120 + row*40 + c8*8)*2u;
        } else {
            int j = i - 1024;                  // 0..1023
            int row = j >> 2, c8 = j & 3;      // 256 rows
            src = Bm + (size_t)row*NSEQ + kc + c8*8;
            dst = stage_b + (uint32_t)(10240 + row*40 + c8*8)*2u;
        }
        CP_ASYNC16(dst, src);
    }
}

__global__ __launch_bounds__(512,1) void av_mma_kernel(
    const __half* __restrict__ Phi16, const __half* __restrict__ Plo16,
    const __half* __restrict__ Vt16,
    float* __restrict__ Qh)
{
    extern __shared__ __align__(16) bf16 sm[];
    const uint32_t smb = smem_u32(sm);
    const int tid = threadIdx.x;
    const int warp = tid >> 5, lane = tid & 31;
    const int wm = warp >> 2, wn = warp & 3;
    const int g = lane >> 2, t4 = lane & 3;
    const int m3 = lane >> 3, rr = lane & 7;
    const int aRowOff = ((m3 & 1) << 3) + rr, aColOff = (m3 >> 1) << 3;
    const int bRowOff = ((m3 >> 1) << 3) + rr, bColOff = (m3 & 1) << 3;
    const int bz = blockIdx.z;
    const int q0 = blockIdx.x * 128;

    const __half* Am[2] = { Phi16 + ((size_t)bz*NSEQ + q0)*NSEQ,
                            Plo16 + ((size_t)bz*NSEQ + q0)*NSEQ };
    const __half* Bm = Vt16 + (size_t)bz*D_*NSEQ;

    float acc[2][8][4] = {};

    av_load_chunk(Am, Bm, smb, 0, tid);  CP_COMMIT();
    av_load_chunk(Am, Bm, smb + AV_STAGE_B, 32, tid);  CP_COMMIT();

    for (int ch = 0; ch < AV_NCHUNK; ch++) {
        uint32_t sbase = smb + (uint32_t)(ch % 3) * AV_STAGE_B;
        CP_WAIT1();
        __syncthreads();
        if (ch + 2 < AV_NCHUNK)
            av_load_chunk(Am, Bm, smb + (uint32_t)((ch+2) % 3) * AV_STAGE_B, (ch+2)*32, tid);
        CP_COMMIT();
        #pragma unroll
        for (int ks = 0; ks < 2; ks++) {
            const int kb0 = ks*16;
            unsigned bF[8][2];
            #pragma unroll
            for (int p = 0; p < 4; p++) {
                int N0 = wn*64 + p*16;
                uint32_t addr = sbase + (uint32_t)(10240 + (N0 + bRowOff)*40 + kb0 + bColOff)*2u;
                unsigned r[4]; ldsm_x4(addr, r);
                bF[2*p  ][0]=r[0]; bF[2*p  ][1]=r[1];
                bF[2*p+1][0]=r[2]; bF[2*p+1][1]=r[3];
            }
            #pragma unroll
            for (int mt = 0; mt < 2; mt++) {
                int R = wm*32 + mt*16;
                unsigned a0[4], a1[4];
                uint32_t abase = sbase + (uint32_t)((R + aRowOff)*40 + kb0 + aColOff)*2u;
                ldsm_x4(abase,          a0);   // Phi16
                ldsm_x4(abase + 10240u, a1);   // Plo16
                #pragma unroll
                for (int nt=0; nt<8; nt++) {
                    mma16816h(acc[mt][nt], a0, bF[nt]);
                    mma16816h(acc[mt][nt], a1, bF[nt]);
                }
            }
        }
    }

    float* ob = Qh + ((size_t)bz*NSEQ + q0)*D_;
    #pragma unroll
    for (int mt=0; mt<2; mt++)
        #pragma unroll
        for (int nt=0; nt<8; nt++) {
            int r = wm*32 + mt*16 + g;
            int c = wn*64 + nt*8 + 2*t4;
            float2 v0 = { acc[mt][nt][0], acc[mt][nt][1] };
            float2 v1 = { acc[mt][nt][2], acc[mt][nt][3] };
            *(float2*)(ob + (size_t)r*D_ + c)     = v0;
            *(float2*)(ob + (size_t)(r+8)*D_ + c) = v1;
        }
}

// ======================= in-place row softmax (4096) + fp16 hi/lo ===========
__device__ __forceinline__ float blockMax256(float v) {
    __shared__ float sh[8];
    #pragma unroll
    for (int o=16;o>0;o>>=1) v = fmaxf(v, __shfl_xor_sync(0xffffffffu, v, o));
    if ((threadIdx.x & 31)==0) sh[threadIdx.x>>5] = v;
    __syncthreads();
    float m = sh[0];
    #pragma unroll
    for (int w=1;w<8;w++) m = fmaxf(m, sh[w]);
    __syncthreads();
    return m;
}
__device__ __forceinline__ float blockSum256(float v) {
    __shared__ float sh[8];
    #pragma unroll
    for (int o=16;o>0;o>>=1) v += __shfl_xor_sync(0xffffffffu, v, o);
    if ((threadIdx.x & 31)==0) sh[threadIdx.x>>5] = v;
    __syncthreads();
    float s = sh[0];
    #pragma unroll
    for (int w=1;w<8;w++) s += sh[w];
    __syncthreads();
    return s;
}
__global__ __launch_bounds__(256) void softmax_kernel(
    float* __restrict__ attn, __half* __restrict__ Phi, __half* __restrict__ Plo)
{
    size_t rb = (size_t)blockIdx.x * NSEQ;
    float4* p = (float4*)(attn + rb);
    int tid = threadIdx.x;
    float4 v[4];
    #pragma unroll
    for (int t=0;t<4;t++) v[t] = p[tid + 256*t];
    float m = -1e30f;
    #pragma unroll
    for (int t=0;t<4;t++)
        m = fmaxf(m, fmaxf(fmaxf(v[t].x, v[t].y), fmaxf(v[t].z, v[t].w)));
    m = blockMax256(m);
    float s = 0.f;
    #pragma unroll
    for (int t=0;t<4;t++) {
        v[t].x = __expf(v[t].x - m); v[t].y = __expf(v[t].y - m);
        v[t].z = __expf(v[t].z - m); v[t].w = __expf(v[t].w - m);
        s += v[t].x + v[t].y + v[t].z + v[t].w;
    }
    s = blockSum256(s);
    float inv = 1.0f / s;
    #pragma unroll
    for (int t=0;t<4;t++) {
        v[t].x *= inv; v[t].y *= inv; v[t].z *= inv; v[t].w *= inv;
        p[tid + 256*t] = v[t];
        int idx = (tid + 256*t)*4;
        float f[4] = {v[t].x, v[t].y, v[t].z, v[t].w};
        __half h[4], l[4];
        #pragma unroll
        for (int u=0;u<4;u++) split_f16(f[u], h[u], l[u]);
        __half2 h01; h01.x=h[0]; h01.y=h[1];
        __half2 h23; h23.x=h[2]; h23.y=h[3];
        __half2 l01; l01.x=l[0]; l01.y=l[1];
        __half2 l23; l23.x=l[2]; l23.y=l[3];
        __half2* hp = (__half2*)(Phi + rb + idx);
        __half2* lp = (__half2*)(Plo + rb + idx);
        hp[0]=h01; hp[1]=h23; lp[0]=l01; lp[1]=l23;
    }
}

// ===================== fused gate epilogue ==================================
__device__ __forceinline__ void blockSum2_128(float& a, float& b) {
    __shared__ float sh[8];
    #pragma unroll
    for (int o=16;o>0;o>>=1) {
        a += __shfl_xor_sync(0xffffffffu, a, o);
        b += __shfl_xor_sync(0xffffffffu, b, o);
    }
    if ((threadIdx.x & 31)==0) { sh[threadIdx.x>>5]=a; sh[4+(threadIdx.x>>5)]=b; }
    __syncthreads();
    a = sh[0]+sh[1]+sh[2]+sh[3];
    b = sh[4]+sh[5]+sh[6]+sh[7];
    __syncthreads();
}

__global__ __launch_bounds__(128) void epilogue_kernel(
    const float* __restrict__ Qg, const float* __restrict__ Qhg,
    const float* __restrict__ W1, const float* __restrict__ b1,
    const float* __restrict__ W2, const float* __restrict__ b2,
    const float* __restrict__ W3, const float* __restrict__ b3,
    const float* __restrict__ Wc, const float* __restrict__ bc,
    const float* __restrict__ Wf, const float* __restrict__ bf,
    const float* __restrict__ gg, const float* __restrict__ gb,
    const float* __restrict__ eg, const float* __restrict__ eb,
    float* __restrict__ out)
{
    __shared__ float Qs[EROWS][D_];
    __shared__ float Qh[EROWS][D_];
    __shared__ float ges[EROWS][NOUT];
    int j = threadIdx.x;
    size_t row0 = (size_t)blockIdx.x * EROWS;

    {
        const float4* s1 = (const float4*)(Qg  + row0*D_);
        const float4* s2 = (const float4*)(Qhg + row0*D_);
        float4* dQ = (float4*)&Qs[0][0];
        float4* dH = (float4*)&Qh[0][0];
        for (int t=j; t<EROWS*D_/4; t+=128) { dQ[t]=s1[t]; dH[t]=s2[t]; }
    }
    __syncthreads();

    float acc1[EROWS]={}, acc2[EROWS]={}, acc3[EROWS]={}, accF[EROWS]={};
    for (int c=0; c<D_; c+=4) {
        float w1v[4], w2v[4], w3v[4], wfv[4];
        #pragma unroll
        for (int u=0;u<4;u++) {
            w1v[u]=W1[(c+u)*NOUT+j]; w2v[u]=W2[(c+u)*NOUT+j];
            w3v[u]=W3[(c+u)*NOUT+j]; wfv[u]=Wf[(c+u)*NOUT+j];
        }
        #pragma unroll
        for (int r=0;r<EROWS;r++) {
            float4 q = *(const float4*)&Qs[r][c];
            float4 h = *(const float4*)&Qh[r][c];
            acc1[r] += q.x*w1v[0]+q.y*w1v[1]+q.z*w1v[2]+q.w*w1v[3];
            accF[r] += q.x*wfv[0]+q.y*wfv[1]+q.z*wfv[2]+q.w*wfv[3];
            acc2[r] += h.x*w2v[0]+h.y*w2v[1]+h.z*w2v[2]+h.w*w2v[3];
            acc3[r] += h.x*w3v[0]+h.y*w3v[1]+h.z*w3v[2]+h.w*w3v[3];
        }
    }

    float bb1=b1[j], bb2=b2[j], bb3=b3[j], bbf=bf[j], bbc=bc[j];
    float ggj=gg[j], gbj=gb[j], egj=eg[j], ebj=eb[j];

    #pragma unroll 1
    for (int r=0;r<EROWS;r++) {
        float gin = fmaxf(fmaxf(acc1[r]+bb1,0.f) + fmaxf(acc2[r]+bb2,0.f), 0.f);
        float ein = fmaxf(acc3[r]+bb3, 0.f);
        float s1 = gin, s2 = gin*gin;
        blockSum2_128(s1, s2);
        float mu  = s1*(1.0f/NOUT);
        float var = s2*(1.0f/NOUT) - mu*mu;
        float G = (gin-mu)*rsqrtf(var+EPS)*ggj + gbj;
        s1 = ein; s2 = ein*ein;
        blockSum2_128(s1, s2);
        mu  = s1*(1.0f/NOUT);
        var = s2*(1.0f/NOUT) - mu*mu;
        float E = (ein-mu)*rsqrtf(var+EPS)*egj + ebj;
        ges[r][j] = G*E;
        accF[r] = fmaxf(accF[r]+bbf, 0.f);
    }
    __syncthreads();

    float accC[EROWS]={};
    for (int k=0;k<NOUT;k++) {
        float wc = Wc[k*NOUT+j];
        #pragma unroll
        for (int r=0;r<EROWS;r++) accC[r] += ges[r][k]*wc;
    }
    #pragma unroll
    for (int r=0;r<EROWS;r++)
        out[(row0+r)*NOUT + j] = accF[r] + fmaxf(accC[r]+bbc, 0.f);
}

// ============================================================================
extern "C" void kernel_launch(void* const* d_in, const int* in_sizes, int n_in,
                              void* d_out, int out_size)
{
    const float* x1 = (const float*)d_in[0];
    const float* x2 = (const float*)d_in[1];
    const float* W_q=(const float*)d_in[2];  const float* b_q=(const float*)d_in[3];
    const float* W_k=(const float*)d_in[4];  const float* b_k=(const float*)d_in[5];
    const float* W_v=(const float*)d_in[6];  const float* b_v=(const float*)d_in[7];
    const float* W1 =(const float*)d_in[8];  const float* b1 =(const float*)d_in[9];
    const float* W2 =(const float*)d_in[10]; const float* b2 =(const float*)d_in[11];
    const float* W3 =(const float*)d_in[12]; const float* b3 =(const float*)d_in[13];
    const float* gg =(const float*)d_in[14]; const float* gb =(const float*)d_in[15];
    const float* eg =(const float*)d_in[16]; const float* eb =(const float*)d_in[17];
    const float* Wc =(const float*)d_in[18]; const float* bc =(const float*)d_in[19];
    const float* Wf =(const float*)d_in[20]; const float* bf =(const float*)d_in[21];

    float* out     = (float*)d_out;
    float* outMain = out;
    float* attn    = out + (size_t)MTOT*NOUT;

    float *Q,*Qh;
    __half *Qhi16,*Qlo16,*K16,*Vt16,*Phi16,*Plo16;
    __half *x1h,*x1l,*x2h,*x2l,*wqh,*wql,*wkh,*wkl,*wvh,*wvl;
    bf16 *tQhi,*tQlo,*tKhi,*tKlo;
    cudaGetSymbolAddress((void**)&Q,     g_Q);
    cudaGetSymbolAddress((void**)&Qh,    g_Qh);
    cudaGetSymbolAddress((void**)&Qhi16, g_Qhi16); cudaGetSymbolAddress((void**)&Qlo16, g_Qlo16);
    cudaGetSymbolAddress((void**)&K16,   g_K16);
    cudaGetSymbolAddress((void**)&tQhi,  g_tQhi);  cudaGetSymbolAddress((void**)&tQlo, g_tQlo);
    cudaGetSymbolAddress((void**)&tKhi,  g_tKhi);  cudaGetSymbolAddress((void**)&tKlo, g_tKlo);
    cudaGetSymbolAddress((void**)&Vt16,  g_Vt16);
    cudaGetSymbolAddress((void**)&Phi16, g_Phi16); cudaGetSymbolAddress((void**)&Plo16, g_Plo16);
    cudaGetSymbolAddress((void**)&x1h, g_x1h); cudaGetSymbolAddress((void**)&x1l, g_x1l);
    cudaGetSymbolAddress((void**)&x2h, g_x2h); cudaGetSymbolAddress((void**)&x2l, g_x2l);
    cudaGetSymbolAddress((void**)&wqh, g_wqh); cudaGetSymbolAddress((void**)&wql, g_wql);
    cudaGetSymbolAddress((void**)&wkh, g_wkh); cudaGetSymbolAddress((void**)&wkl, g_wkl);
    cudaGetSymbolAddress((void**)&wvh, g_wvh); cudaGetSymbolAddress((void**)&wvl, g_wvl);

    cudaFuncSetAttribute(scores_mma_kernel, cudaFuncAttributeMaxDynamicSharedMemorySize, 3*SC_STAGE_B);
    cudaFuncSetAttribute(av_mma_kernel,     cudaFuncAttributeMaxDynamicSharedMemorySize, 3*AV_STAGE_B);
    cudaFuncSetAttribute(proj_mma_kernel<0>, cudaFuncAttributeMaxDynamicSharedMemorySize, 3*PJ_STAGE_B);
    cudaFuncSetAttribute(proj_mma_kernel<1>, cudaFuncAttributeMaxDynamicSharedMemorySize, 3*PJ_STAGE_B);
    cudaFuncSetAttribute(proj_mma_kernel<2>, cudaFuncAttributeMaxDynamicSharedMemorySize, 3*PJ_STAGE_B);

    convert_x_kernel<<<MTOT*D_/4/256, 256>>>(x2, x2h, x2l);
    convert_x_kernel<<<MTOT*D_/4/256, 256>>>(x1, x1h, x1l);
    convert_wt_kernel<<<D_, D_>>>(W_q, wqh, wql);
    convert_wt_kernel<<<D_, D_>>>(W_k, wkh, wkl);
    convert_wt_kernel<<<D_, D_>>>(W_v, wvh, wvl);

    proj_mma_kernel<0><<<MTOT/128, 512, 3*PJ_STAGE_B>>>(
        x2h, x2l, wqh, wql, b_q, Q, Qhi16, Qlo16, tQhi, tQlo);
    proj_mma_kernel<1><<<MTOT/128, 512, 3*PJ_STAGE_B>>>(
        x1h, x1l, wkh, wkl, b_k, nullptr, K16, nullptr, tKhi, tKlo);
    proj_mma_kernel<2><<<MTOT/128, 512, 3*PJ_STAGE_B>>>(
        x1h, x1l, wvh, wvl, b_v, nullptr, Vt16, nullptr, nullptr, nullptr);

    scores_mma_kernel<<<dim3(NSEQ/128, NSEQ/128, B_), 512, 3*SC_STAGE_B>>>(
        Qhi16, Qlo16, tQhi, tQlo, K16, tKhi, tKlo, attn);

    softmax_kernel<<<MTOT, 256>>>(attn, Phi16, Plo16);

    av_mma_kernel<<<dim3(NSEQ/128, 1, B_), 512, 3*AV_STAGE_B>>>(Phi16, Plo16, Vt16, Qh);

    epilogue_kernel<<<MTOT/EROWS, 128>>>(Q, Qh, W1,b1, W2,b2, W3,b3,
                                         Wc,bc, Wf,bf, gg,gb, eg,eb, outMain);
}

// round 14
// speedup vs baseline: 1.5934x; 1.5934x over previous
#include <cuda_runtime.h>
#include <cuda_bf16.h>
#include <cuda_fp16.h>
#include <stdint.h>
#include <math.h>

#define B_    4
#define NSEQ  4096
#define MTOT  (B_*NSEQ)
#define D_    256
#define NOUT  128
#define EPS   1e-5f
#define EROWS 16

typedef __nv_bfloat16 bf16;

// ---- scratch (static device globals; no allocation allowed) ----
__device__ float  g_Q [(size_t)MTOT*D_];
__device__ float  g_Qh[(size_t)MTOT*D_];
__device__ __half g_Qhi16[(size_t)MTOT*D_], g_Qlo16[(size_t)MTOT*D_];
__device__ __half g_K16  [(size_t)MTOT*D_];
__device__ __half g_tQh16[(size_t)MTOT*D_], g_tQl16[(size_t)MTOT*D_];
__device__ __half g_tK16 [(size_t)MTOT*D_];
__device__ __half g_Vt16[(size_t)MTOT*D_];                           // [B][D][NSEQ]
__device__ __half g_Phi16[(size_t)B_*NSEQ*NSEQ], g_Plo16[(size_t)B_*NSEQ*NSEQ];

__device__ __forceinline__ void split_f16(float x, __half& h, __half& l) {
    h = __float2half_rn(x);
    l = __float2half_rn(x - __half2float(h));
}

__device__ __forceinline__ uint32_t smem_u32(const void* p) {
    uint32_t a;
    asm("{ .reg .u64 t; cvta.to.shared.u64 t, %1; cvt.u32.u64 %0, t; }" : "=r"(a) : "l"(p));
    return a;
}

#define CP_ASYNC16(dst, src) \
    asm volatile("cp.async.cg.shared.global [%0], [%1], 16;" :: "r"(dst), "l"(src) : "memory")
#define CP_COMMIT() asm volatile("cp.async.commit_group;" ::: "memory")
#define CP_WAIT1()  asm volatile("cp.async.wait_group 1;" ::: "memory")

// fp16 m16n8k16 mma, fp32 accum
__device__ __forceinline__ void mma16816h(float* d, const unsigned* a, const unsigned* b) {
    asm volatile(
        "mma.sync.aligned.m16n8k16.row.col.f32.f16.f16.f32 "
        "{%0,%1,%2,%3}, {%4,%5,%6,%7}, {%8,%9}, {%0,%1,%2,%3};\n"
        : "+f"(d[0]), "+f"(d[1]), "+f"(d[2]), "+f"(d[3])
        : "r"(a[0]), "r"(a[1]), "r"(a[2]), "r"(a[3]), "r"(b[0]), "r"(b[1]));
}

__device__ __forceinline__ void ldsm_x4(uint32_t addr, unsigned* r) {
    asm volatile("ldmatrix.sync.aligned.m8n8.x4.shared.b16 {%0,%1,%2,%3}, [%4];"
        : "=r"(r[0]), "=r"(r[1]), "=r"(r[2]), "=r"(r[3]) : "r"(addr));
}

// ================= Q projection: Q = x2@Wq + bq ============================
__global__ __launch_bounds__(256) void proj_q_kernel(
    const float* __restrict__ X, const float* __restrict__ W,
    const float* __restrict__ bias, float* __restrict__ Cf,
    __half* __restrict__ H1, __half* __restrict__ L1,
    __half* __restrict__ H2, __half* __restrict__ L2)
{
    const int BM=64, BN=64, BK=16;
    __shared__ float Xs[BK][BM];
    __shared__ float Ws[BK][BN];
    int tid = threadIdx.x;
    int tx = tid & 15, ty = tid >> 4;
    int row0 = blockIdx.y * BM;
    int col0 = blockIdx.x * BN;
    int lr = tid >> 2, lc4 = tid & 3;
    int wkr = tid >> 4, wc4 = tid & 15;
    float acc[4][4] = {};

    for (int k0 = 0; k0 < D_; k0 += BK) {
        float4 v = *(const float4*)(X + (size_t)(row0+lr)*D_ + k0 + lc4*4);
        Xs[lc4*4+0][lr]=v.x; Xs[lc4*4+1][lr]=v.y; Xs[lc4*4+2][lr]=v.z; Xs[lc4*4+3][lr]=v.w;
        *(float4*)&Ws[wkr][wc4*4] = *(const float4*)(W + (size_t)(k0+wkr)*D_ + col0 + wc4*4);
        __syncthreads();
        #pragma unroll
        for (int kk=0; kk<BK; kk++) {
            float4 a4 = *(const float4*)&Xs[kk][ty*4];
            float4 w4 = *(const float4*)&Ws[kk][tx*4];
            float av[4]={a4.x,a4.y,a4.z,a4.w}, wv[4]={w4.x,w4.y,w4.z,w4.w};
            #pragma unroll
            for (int i=0;i<4;i++)
                #pragma unroll
                for (int j=0;j<4;j++) acc[i][j] += av[i]*wv[j];
        }
        __syncthreads();
    }
    #pragma unroll
    for (int i=0;i<4;i++) {
        size_t r = row0 + ty*4 + i;
        #pragma unroll
        for (int j=0;j<4;j++) {
            int cix = col0 + tx*4 + j;
            float val = acc[i][j] + bias[cix];
            Cf[r*D_ + cix] = val;
            __half hh,hl; split_f16(val, hh, hl);
            H1[r*D_+cix]=hh; L1[r*D_+cix]=hl;
            float t = tanhf(val);
            split_f16(t, hh, hl);
            H2[r*D_+cix]=hh; L2[r*D_+cix]=hl;
        }
    }
}

// ============== merged K+V projection from x1 ==============================
__global__ __launch_bounds__(256) void proj_kv_kernel(
    const float* __restrict__ X,
    const float* __restrict__ Wk, const float* __restrict__ bk,
    const float* __restrict__ Wv, const float* __restrict__ bv,
    __half* __restrict__ K16, __half* __restrict__ tK16,
    __half* __restrict__ Vt16)
{
    const int BM=64, BN=64, BK=16;
    __shared__ float Xs [BK][BM];
    __shared__ float WsK[BK][BN];
    __shared__ float WsV[BK][BN];
    int tid = threadIdx.x;
    int tx = tid & 15, ty = tid >> 4;
    int row0 = blockIdx.y * BM;
    int col0 = blockIdx.x * BN;
    int lr = tid >> 2, lc4 = tid & 3;
    int wkr = tid >> 4, wc4 = tid & 15;
    float accK[4][4] = {}, accV[4][4] = {};

    for (int k0 = 0; k0 < D_; k0 += BK) {
        float4 v = *(const float4*)(X + (size_t)(row0+lr)*D_ + k0 + lc4*4);
        Xs[lc4*4+0][lr]=v.x; Xs[lc4*4+1][lr]=v.y; Xs[lc4*4+2][lr]=v.z; Xs[lc4*4+3][lr]=v.w;
        *(float4*)&WsK[wkr][wc4*4] = *(const float4*)(Wk + (size_t)(k0+wkr)*D_ + col0 + wc4*4);
        *(float4*)&WsV[wkr][wc4*4] = *(const float4*)(Wv + (size_t)(k0+wkr)*D_ + col0 + wc4*4);
        __syncthreads();
        #pragma unroll
        for (int kk=0; kk<BK; kk++) {
            float4 a4 = *(const float4*)&Xs[kk][ty*4];
            float4 k4 = *(const float4*)&WsK[kk][tx*4];
            float4 v4 = *(const float4*)&WsV[kk][tx*4];
            float av[4]={a4.x,a4.y,a4.z,a4.w};
            float kv[4]={k4.x,k4.y,k4.z,k4.w}, vv[4]={v4.x,v4.y,v4.z,v4.w};
            #pragma unroll
            for (int i=0;i<4;i++)
                #pragma unroll
                for (int j=0;j<4;j++) {
                    accK[i][j] += av[i]*kv[j];
                    accV[i][j] += av[i]*vv[j];
                }
        }
        __syncthreads();
    }
    #pragma unroll
    for (int i=0;i<4;i++) {
        size_t r = row0 + ty*4 + i;
        int b = (int)(r >> 12), s = (int)(r & 4095);
        #pragma unroll
        for (int j=0;j<4;j++) {
            int cix = col0 + tx*4 + j;
            float valK = accK[i][j] + bk[cix];
            K16[r*D_+cix] = __float2half_rn(valK);
            tK16[r*D_+cix] = __float2half_rn(tanhf(valK));
            float valV = accV[i][j] + bv[cix];
            size_t ti = ((size_t)b*D_ + cix)*NSEQ + s;
            Vt16[ti] = __float2half_rn(valV);
        }
    }
}

// ====== dual-GEMM scores: 6 fp16 mats, asym QK + asym tanh =================
// stage: mats 0..5 = Qhi,Qlo,tQh,tQl (A, q0-based), K16,tK16 (B, c0-based)
// mat m at m*5120 el, rows padded to 40 el. stage = 6*5120 el = 61440 B.
#define SC_STAGE_B  61440

__device__ __forceinline__ void sc_load_chunk(
    const __half* const* P, uint32_t stage_b, int kc, int tid)
{
    #pragma unroll
    for (int t=0;t<6;t++) {
        int i = tid + t*512;                    // 0..3071
        int m = i >> 9, rem = i & 511, row = rem >> 2, c8 = rem & 3;
        const __half* src = P[m] + (size_t)row*D_ + kc + c8*8;
        uint32_t dst = stage_b + (uint32_t)(m*5120 + row*40 + c8*8)*2u;
        CP_ASYNC16(dst, src);
    }
}

__global__ __launch_bounds__(512,1) void scores_mma_kernel(
    const __half* __restrict__ Qhi16, const __half* __restrict__ Qlo16,
    const __half* __restrict__ tQh16, const __half* __restrict__ tQl16,
    const __half* __restrict__ K16, const __half* __restrict__ tK16,
    float* __restrict__ attn)
{
    extern __shared__ __align__(16) bf16 sm[];
    const uint32_t smb = smem_u32(sm);
    const int tid = threadIdx.x;
    const int warp = tid >> 5, lane = tid & 31;
    const int wm = warp >> 2, wn = warp & 3;
    const int g = lane >> 2, t4 = lane & 3;
    const int m3 = lane >> 3, rr = lane & 7;
    const int aRowOff = ((m3 & 1) << 3) + rr, aColOff = (m3 >> 1) << 3;
    const int bRowOff = ((m3 >> 1) << 3) + rr, bColOff = (m3 & 1) << 3;
    const int bz = blockIdx.z;
    const int q0 = blockIdx.y * 128, c0 = blockIdx.x * 128;

    const __half* P[6] = {
        Qhi16 + ((size_t)bz*NSEQ + q0)*D_,
        Qlo16 + ((size_t)bz*NSEQ + q0)*D_,
        tQh16 + ((size_t)bz*NSEQ + q0)*D_,
        tQl16 + ((size_t)bz*NSEQ + q0)*D_,
        K16   + ((size_t)bz*NSEQ + c0)*D_,
        tK16  + ((size_t)bz*NSEQ + c0)*D_ };

    float accQ[2][4][4] = {};
    float accT[2][4][4] = {};

    sc_load_chunk(P, smb, 0, tid);  CP_COMMIT();
    sc_load_chunk(P, smb + SC_STAGE_B, 32, tid);  CP_COMMIT();

    for (int ch = 0; ch < 8; ch++) {
        uint32_t sbase = smb + (uint32_t)(ch % 3) * SC_STAGE_B;
        CP_WAIT1();
        __syncthreads();
        if (ch + 2 < 8)
            sc_load_chunk(P, smb + (uint32_t)((ch+2) % 3) * SC_STAGE_B, (ch+2)*32, tid);
        CP_COMMIT();
        #pragma unroll
        for (int ks = 0; ks < 2; ks++) {
            const int kb0 = ks*16;
            // B fragments: mats 4 (K16), 5 (tK16)
            unsigned bF[2][4][2];
            #pragma unroll
            for (int mb = 0; mb < 2; mb++)
                #pragma unroll
                for (int p = 0; p < 2; p++) {
                    int N0 = wn*32 + p*16;
                    uint32_t addr = sbase + (uint32_t)((4+mb)*5120 + (N0 + bRowOff)*40 + kb0 + bColOff)*2u;
                    unsigned r[4]; ldsm_x4(addr, r);
                    bF[mb][2*p  ][0]=r[0]; bF[mb][2*p  ][1]=r[1];
                    bF[mb][2*p+1][0]=r[2]; bF[mb][2*p+1][1]=r[3];
                }
            #pragma unroll
            for (int mt = 0; mt < 2; mt++) {
                int R = wm*32 + mt*16;
                unsigned a0[4], a1[4], a2[4], a3[4];
                uint32_t abase = sbase + (uint32_t)((R + aRowOff)*40 + kb0 + aColOff)*2u;
                ldsm_x4(abase,            a0);   // Qhi16
                ldsm_x4(abase + 10240u,   a1);   // Qlo16
                ldsm_x4(abase + 20480u,   a2);   // tQh16
                ldsm_x4(abase + 30720u,   a3);   // tQl16
                #pragma unroll
                for (int nt=0; nt<4; nt++) {
                    mma16816h(accQ[mt][nt], a0, bF[0][nt]);
                    mma16816h(accQ[mt][nt], a1, bF[0][nt]);
                    mma16816h(accT[mt][nt], a2, bF[1][nt]);
                    mma16816h(accT[mt][nt], a3, bF[1][nt]);
                }
            }
        }
    }

    float* ob = attn + (size_t)bz*NSEQ*NSEQ;
    #pragma unroll
    for (int mt=0; mt<2; mt++)
        #pragma unroll
        for (int nt=0; nt<4; nt++) {
            int r = q0 + wm*32 + mt*16 + g;
            int c = c0 + wn*32 + nt*8 + 2*t4;
            const float* aq = accQ[mt][nt];
            const float* at = accT[mt][nt];
            float2 v0 = { aq[0]*(at[0]+1.0f)*0.03125f, aq[1]*(at[1]+1.0f)*0.03125f };
            float2 v1 = { aq[2]*(at[2]+1.0f)*0.03125f, aq[3]*(at[3]+1.0f)*0.03125f };
            *(float2*)(ob + (size_t)r*NSEQ + c)     = v0;
            *(float2*)(ob + (size_t)(r+8)*NSEQ + c) = v1;
        }
}

// ========= Qhat = attn @ V — fp16 asym: P hi/lo fp16 × V fp16 ===============
#define AV_STAGE_B  40960
#define AV_NCHUNK  (NSEQ/32)

__device__ __forceinline__ void av_load_chunk(
    const __half* const* Am, const __half* Bm, uint32_t stage_b, int kc, int tid)
{
    #pragma unroll
    for (int t=0;t<4;t++) {
        int i = tid + t*512;                   // 0..2047
        const __half* src; uint32_t dst;
        if (i < 1024) {
            int m = i >> 9, rem = i & 511, row = rem >> 2, c8 = rem & 3;
            src = Am[m] + (size_t)row*NSEQ + kc + c8*8;
            dst = stage_b + (uint32_t)(m*5120 + row*40 + c8*8)*2u;
        } else {
            int j = i - 1024;                  // 0..1023
            int row = j >> 2, c8 = j & 3;      // 256 rows
            src = Bm + (size_t)row*NSEQ + kc + c8*8;
            dst = stage_b + (uint32_t)(10240 + row*40 + c8*8)*2u;
        }
        CP_ASYNC16(dst, src);
    }
}

__global__ __launch_bounds__(512,1) void av_mma_kernel(
    const __half* __restrict__ Phi16, const __half* __restrict__ Plo16,
    const __half* __restrict__ Vt16,
    float* __restrict__ Qh)
{
    extern __shared__ __align__(16) bf16 sm[];
    const uint32_t smb = smem_u32(sm);
    const int tid = threadIdx.x;
    const int warp = tid >> 5, lane = tid & 31;
    const int wm = warp >> 2, wn = warp & 3;
    const int g = lane >> 2, t4 = lane & 3;
    const int m3 = lane >> 3, rr = lane & 7;
    const int aRowOff = ((m3 & 1) << 3) + rr, aColOff = (m3 >> 1) << 3;
    const int bRowOff = ((m3 >> 1) << 3) + rr, bColOff = (m3 & 1) << 3;
    const int bz = blockIdx.z;
    const int q0 = blockIdx.x * 128;

    const __half* Am[2] = { Phi16 + ((size_t)bz*NSEQ + q0)*NSEQ,
                            Plo16 + ((size_t)bz*NSEQ + q0)*NSEQ };
    const __half* Bm = Vt16 + (size_t)bz*D_*NSEQ;

    float acc[2][8][4] = {};

    av_load_chunk(Am, Bm, smb, 0, tid);  CP_COMMIT();
    av_load_chunk(Am, Bm, smb + AV_STAGE_B, 32, tid);  CP_COMMIT();

    for (int ch = 0; ch < AV_NCHUNK; ch++) {
        uint32_t sbase = smb + (uint32_t)(ch % 3) * AV_STAGE_B;
        CP_WAIT1();
        __syncthreads();
        if (ch + 2 < AV_NCHUNK)
            av_load_chunk(Am, Bm, smb + (uint32_t)((ch+2) % 3) * AV_STAGE_B, (ch+2)*32, tid);
        CP_COMMIT();
        #pragma unroll
        for (int ks = 0; ks < 2; ks++) {
            const int kb0 = ks*16;
            unsigned bF[8][2];
            #pragma unroll
            for (int p = 0; p < 4; p++) {
                int N0 = wn*64 + p*16;
                uint32_t addr = sbase + (uint32_t)(10240 + (N0 + bRowOff)*40 + kb0 + bColOff)*2u;
                unsigned r[4]; ldsm_x4(addr, r);
                bF[2*p  ][0]=r[0]; bF[2*p  ][1]=r[1];
                bF[2*p+1][0]=r[2]; bF[2*p+1][1]=r[3];
            }
            #pragma unroll
            for (int mt = 0; mt < 2; mt++) {
                int R = wm*32 + mt*16;
                unsigned a0[4], a1[4];
                uint32_t abase = sbase + (uint32_t)((R + aRowOff)*40 + kb0 + aColOff)*2u;
                ldsm_x4(abase,          a0);   // Phi16
                ldsm_x4(abase + 10240u, a1);   // Plo16
                #pragma unroll
                for (int nt=0; nt<8; nt++) {
                    mma16816h(acc[mt][nt], a0, bF[nt]);
                    mma16816h(acc[mt][nt], a1, bF[nt]);
                }
            }
        }
    }

    float* ob = Qh + ((size_t)bz*NSEQ + q0)*D_;
    #pragma unroll
    for (int mt=0; mt<2; mt++)
        #pragma unroll
        for (int nt=0; nt<8; nt++) {
            int r = wm*32 + mt*16 + g;
            int c = wn*64 + nt*8 + 2*t4;
            float2 v0 = { acc[mt][nt][0], acc[mt][nt][1] };
            float2 v1 = { acc[mt][nt][2], acc[mt][nt][3] };
            *(float2*)(ob + (size_t)r*D_ + c)     = v0;
            *(float2*)(ob + (size_t)(r+8)*D_ + c) = v1;
        }
}

// ======================= in-place row softmax (4096) + fp16 hi/lo ===========
__device__ __forceinline__ float blockMax256(float v) {
    __shared__ float sh[8];
    #pragma unroll
    for (int o=16;o>0;o>>=1) v = fmaxf(v, __shfl_xor_sync(0xffffffffu, v, o));
    if ((threadIdx.x & 31)==0) sh[threadIdx.x>>5] = v;
    __syncthreads();
    float m = sh[0];
    #pragma unroll
    for (int w=1;w<8;w++) m = fmaxf(m, sh[w]);
    __syncthreads();
    return m;
}
__device__ __forceinline__ float blockSum256(float v) {
    __shared__ float sh[8];
    #pragma unroll
    for (int o=16;o>0;o>>=1) v += __shfl_xor_sync(0xffffffffu, v, o);
    if ((threadIdx.x & 31)==0) sh[threadIdx.x>>5] = v;
    __syncthreads();
    float s = sh[0];
    #pragma unroll
    for (int w=1;w<8;w++) s += sh[w];
    __syncthreads();
    return s;
}
__global__ __launch_bounds__(256) void softmax_kernel(
    float* __restrict__ attn, __half* __restrict__ Phi, __half* __restrict__ Plo)
{
    size_t rb = (size_t)blockIdx.x * NSEQ;
    float4* p = (float4*)(attn + rb);
    int tid = threadIdx.x;
    float4 v[4];
    #pragma unroll
    for (int t=0;t<4;t++) v[t] = p[tid + 256*t];
    float m = -1e30f;
    #pragma unroll
    for (int t=0;t<4;t++)
        m = fmaxf(m, fmaxf(fmaxf(v[t].x, v[t].y), fmaxf(v[t].z, v[t].w)));
    m = blockMax256(m);
    float s = 0.f;
    #pragma unroll
    for (int t=0;t<4;t++) {
        v[t].x = __expf(v[t].x - m); v[t].y = __expf(v[t].y - m);
        v[t].z = __expf(v[t].z - m); v[t].w = __expf(v[t].w - m);
        s += v[t].x + v[t].y + v[t].z + v[t].w;
    }
    s = blockSum256(s);
    float inv = 1.0f / s;
    #pragma unroll
    for (int t=0;t<4;t++) {
        v[t].x *= inv; v[t].y *= inv; v[t].z *= inv; v[t].w *= inv;
        p[tid + 256*t] = v[t];
        int idx = (tid + 256*t)*4;
        float f[4] = {v[t].x, v[t].y, v[t].z, v[t].w};
        __half h[4], l[4];
        #pragma unroll
        for (int u=0;u<4;u++) split_f16(f[u], h[u], l[u]);
        __half2 h01; h01.x=h[0]; h01.y=h[1];
        __half2 h23; h23.x=h[2]; h23.y=h[3];
        __half2 l01; l01.x=l[0]; l01.y=l[1];
        __half2 l23; l23.x=l[2]; l23.y=l[3];
        __half2* hp = (__half2*)(Phi + rb + idx);
        __half2* lp = (__half2*)(Plo + rb + idx);
        hp[0]=h01; hp[1]=h23; lp[0]=l01; lp[1]=l23;
    }
}

// ===================== fused gate epilogue ==================================
__device__ __forceinline__ void blockSum2_128(float& a, float& b) {
    __shared__ float sh[8];
    #pragma unroll
    for (int o=16;o>0;o>>=1) {
        a += __shfl_xor_sync(0xffffffffu, a, o);
        b += __shfl_xor_sync(0xffffffffu, b, o);
    }
    if ((threadIdx.x & 31)==0) { sh[threadIdx.x>>5]=a; sh[4+(threadIdx.x>>5)]=b; }
    __syncthreads();
    a = sh[0]+sh[1]+sh[2]+sh[3];
    b = sh[4]+sh[5]+sh[6]+sh[7];
    __syncthreads();
}

__global__ __launch_bounds__(128) void epilogue_kernel(
    const float* __restrict__ Qg, const float* __restrict__ Qhg,
    const float* __restrict__ W1, const float* __restrict__ b1,
    const float* __restrict__ W2, const float* __restrict__ b2,
    const float* __restrict__ W3, const float* __restrict__ b3,
    const float* __restrict__ Wc, const float* __restrict__ bc,
    const float* __restrict__ Wf, const float* __restrict__ bf,
    const float* __restrict__ gg, const float* __restrict__ gb,
    const float* __restrict__ eg, const float* __restrict__ eb,
    float* __restrict__ out)
{
    __shared__ float Qs[EROWS][D_];
    __shared__ float Qh[EROWS][D_];
    __shared__ float ges[EROWS][NOUT];
    int j = threadIdx.x;
    size_t row0 = (size_t)blockIdx.x * EROWS;

    {
        const float4* s1 = (const float4*)(Qg  + row0*D_);
        const float4* s2 = (const float4*)(Qhg + row0*D_);
        float4* dQ = (float4*)&Qs[0][0];
        float4* dH = (float4*)&Qh[0][0];
        for (int t=j; t<EROWS*D_/4; t+=128) { dQ[t]=s1[t]; dH[t]=s2[t]; }
    }
    __syncthreads();

    float acc1[EROWS]={}, acc2[EROWS]={}, acc3[EROWS]={}, accF[EROWS]={};
    for (int c=0; c<D_; c+=4) {
        float w1v[4], w2v[4], w3v[4], wfv[4];
        #pragma unroll
        for (int u=0;u<4;u++) {
            w1v[u]=W1[(c+u)*NOUT+j]; w2v[u]=W2[(c+u)*NOUT+j];
            w3v[u]=W3[(c+u)*NOUT+j]; wfv[u]=Wf[(c+u)*NOUT+j];
        }
        #pragma unroll
        for (int r=0;r<EROWS;r++) {
            float4 q = *(const float4*)&Qs[r][c];
            float4 h = *(const float4*)&Qh[r][c];
            acc1[r] += q.x*w1v[0]+q.y*w1v[1]+q.z*w1v[2]+q.w*w1v[3];
            accF[r] += q.x*wfv[0]+q.y*wfv[1]+q.z*wfv[2]+q.w*wfv[3];
            acc2[r] += h.x*w2v[0]+h.y*w2v[1]+h.z*w2v[2]+h.w*w2v[3];
            acc3[r] += h.x*w3v[0]+h.y*w3v[1]+h.z*w3v[2]+h.w*w3v[3];
        }
    }

    float bb1=b1[j], bb2=b2[j], bb3=b3[j], bbf=bf[j], bbc=bc[j];
    float ggj=gg[j], gbj=gb[j], egj=eg[j], ebj=eb[j];

    #pragma unroll 1
    for (int r=0;r<EROWS;r++) {
        float gin = fmaxf(fmaxf(acc1[r]+bb1,0.f) + fmaxf(acc2[r]+bb2,0.f), 0.f);
        float ein = fmaxf(acc3[r]+bb3, 0.f);
        float s1 = gin, s2 = gin*gin;
        blockSum2_128(s1, s2);
        float mu  = s1*(1.0f/NOUT);
        float var = s2*(1.0f/NOUT) - mu*mu;
        float G = (gin-mu)*rsqrtf(var+EPS)*ggj + gbj;
        s1 = ein; s2 = ein*ein;
        blockSum2_128(s1, s2);
        mu  = s1*(1.0f/NOUT);
        var = s2*(1.0f/NOUT) - mu*mu;
        float E = (ein-mu)*rsqrtf(var+EPS)*egj + ebj;
        ges[r][j] = G*E;
        accF[r] = fmaxf(accF[r]+bbf, 0.f);
    }
    __syncthreads();

    float accC[EROWS]={};
    for (int k=0;k<NOUT;k++) {
        float wc = Wc[k*NOUT+j];
        #pragma unroll
        for (int r=0;r<EROWS;r++) accC[r] += ges[r][k]*wc;
    }
    #pragma unroll
    for (int r=0;r<EROWS;r++)
        out[(row0+r)*NOUT + j] = accF[r] + fmaxf(accC[r]+bbc, 0.f);
}

// ============================================================================
extern "C" void kernel_launch(void* const* d_in, const int* in_sizes, int n_in,
                              void* d_out, int out_size)
{
    const float* x1 = (const float*)d_in[0];
    const float* x2 = (const float*)d_in[1];
    const float* W_q=(const float*)d_in[2];  const float* b_q=(const float*)d_in[3];
    const float* W_k=(const float*)d_in[4];  const float* b_k=(const float*)d_in[5];
    const float* W_v=(const float*)d_in[6];  const float* b_v=(const float*)d_in[7];
    const float* W1 =(const float*)d_in[8];  const float* b1 =(const float*)d_in[9];
    const float* W2 =(const float*)d_in[10]; const float* b2 =(const float*)d_in[11];
    const float* W3 =(const float*)d_in[12]; const float* b3 =(const float*)d_in[13];
    const float* gg =(const float*)d_in[14]; const float* gb =(const float*)d_in[15];
    const float* eg =(const float*)d_in[16]; const float* eb =(const float*)d_in[17];
    const float* Wc =(const float*)d_in[18]; const float* bc =(const float*)d_in[19];
    const float* Wf =(const float*)d_in[20]; const float* bf =(const float*)d_in[21];

    float* out     = (float*)d_out;
    float* outMain = out;
    float* attn    = out + (size_t)MTOT*NOUT;

    float *Q,*Qh;
    __half *Qhi16,*Qlo16,*K16,*tQh16,*tQl16,*tK16,*Vt16,*Phi16,*Plo16;
    cudaGetSymbolAddress((void**)&Q,     g_Q);
    cudaGetSymbolAddress((void**)&Qh,    g_Qh);
    cudaGetSymbolAddress((void**)&Qhi16, g_Qhi16); cudaGetSymbolAddress((void**)&Qlo16, g_Qlo16);
    cudaGetSymbolAddress((void**)&K16,   g_K16);
    cudaGetSymbolAddress((void**)&tQh16, g_tQh16); cudaGetSymbolAddress((void**)&tQl16, g_tQl16);
    cudaGetSymbolAddress((void**)&tK16,  g_tK16);
    cudaGetSymbolAddress((void**)&Vt16,  g_Vt16);
    cudaGetSymbolAddress((void**)&Phi16, g_Phi16); cudaGetSymbolAddress((void**)&Plo16, g_Plo16);

    cudaFuncSetAttribute(scores_mma_kernel, cudaFuncAttributeMaxDynamicSharedMemorySize, 3*SC_STAGE_B);
    cudaFuncSetAttribute(av_mma_kernel,     cudaFuncAttributeMaxDynamicSharedMemorySize, 3*AV_STAGE_B);

    dim3 pg(D_/64, MTOT/64);
    proj_q_kernel <<<pg, 256>>>(x2, W_q, b_q, Q, Qhi16, Qlo16, tQh16, tQl16);
    proj_kv_kernel<<<pg, 256>>>(x1, W_k, b_k, W_v, b_v, K16, tK16, Vt16);

    scores_mma_kernel<<<dim3(NSEQ/128, NSEQ/128, B_), 512, 3*SC_STAGE_B>>>(
        Qhi16, Qlo16, tQh16, tQl16, K16, tK16, attn);

    softmax_kernel<<<MTOT, 256>>>(attn, Phi16, Plo16);

    av_mma_kernel<<<dim3(NSEQ/128, 1, B_), 512, 3*AV_STAGE_B>>>(Phi16, Plo16, Vt16, Qh);

    epilogue_kernel<<<MTOT/EROWS, 128>>>(Q, Qh, W1,b1, W2,b2, W3,b3,
                                         Wc,bc, Wf,bf, gg,gb, eg,eb, outMain);
}

// round 15
// speedup vs baseline: 1.7419x; 1.0932x over previous
#include <cuda_runtime.h>
#include <cuda_bf16.h>
#include <cuda_fp16.h>
#include <stdint.h>
#include <math.h>

#define B_    4
#define NSEQ  4096
#define MTOT  (B_*NSEQ)
#define D_    256
#define NOUT  128
#define EPS   1e-5f
#define EROWS 16

typedef __nv_bfloat16 bf16;

// ---- scratch (static device globals; no allocation allowed) ----
__device__ float  g_Q [(size_t)MTOT*D_];
__device__ float  g_Qh[(size_t)MTOT*D_];
__device__ __half g_Qhi16[(size_t)MTOT*D_], g_Qlo16[(size_t)MTOT*D_];
__device__ __half g_K16  [(size_t)MTOT*D_];
__device__ __half g_tQh16[(size_t)MTOT*D_], g_tQl16[(size_t)MTOT*D_];
__device__ __half g_tK16 [(size_t)MTOT*D_];
__device__ __half g_Vt16[(size_t)MTOT*D_];                           // [B][D][NSEQ]
__device__ __half g_Phi16[(size_t)B_*NSEQ*NSEQ], g_Plo16[(size_t)B_*NSEQ*NSEQ];
// fp16 hi/lo of inputs + transposed weights
__device__ __half g_x1h[(size_t)MTOT*D_], g_x1l[(size_t)MTOT*D_];
__device__ __half g_x2h[(size_t)MTOT*D_], g_x2l[(size_t)MTOT*D_];
__device__ __half g_wqh[D_*D_], g_wql[D_*D_];
__device__ __half g_wkh[D_*D_], g_wkl[D_*D_];
__device__ __half g_wvh[D_*D_], g_wvl[D_*D_];

__device__ __forceinline__ void split_f16(float x, __half& h, __half& l) {
    h = __float2half_rn(x);
    l = __float2half_rn(x - __half2float(h));
}

__device__ __forceinline__ uint32_t smem_u32(const void* p) {
    uint32_t a;
    asm("{ .reg .u64 t; cvta.to.shared.u64 t, %1; cvt.u32.u64 %0, t; }" : "=r"(a) : "l"(p));
    return a;
}

#define CP_ASYNC16(dst, src) \
    asm volatile("cp.async.cg.shared.global [%0], [%1], 16;" :: "r"(dst), "l"(src) : "memory")
#define CP_COMMIT() asm volatile("cp.async.commit_group;" ::: "memory")
#define CP_WAIT1()  asm volatile("cp.async.wait_group 1;" ::: "memory")

// fp16 m16n8k16 mma, fp32 accum
__device__ __forceinline__ void mma16816h(float* d, const unsigned* a, const unsigned* b) {
    asm volatile(
        "mma.sync.aligned.m16n8k16.row.col.f32.f16.f16.f32 "
        "{%0,%1,%2,%3}, {%4,%5,%6,%7}, {%8,%9}, {%0,%1,%2,%3};\n"
        : "+f"(d[0]), "+f"(d[1]), "+f"(d[2]), "+f"(d[3])
        : "r"(a[0]), "r"(a[1]), "r"(a[2]), "r"(a[3]), "r"(b[0]), "r"(b[1]));
}

__device__ __forceinline__ void ldsm_x4(uint32_t addr, unsigned* r) {
    asm volatile("ldmatrix.sync.aligned.m8n8.x4.shared.b16 {%0,%1,%2,%3}, [%4];"
        : "=r"(r[0]), "=r"(r[1]), "=r"(r[2]), "=r"(r[3]) : "r"(addr));
}

// ================= converts =================================================
__global__ __launch_bounds__(256) void convert_x_kernel(
    const float* __restrict__ x, __half* __restrict__ xh, __half* __restrict__ xl)
{
    int i = blockIdx.x*256 + threadIdx.x;          // over float4 units
    float4 v = ((const float4*)x)[i];
    __half h[4], l[4];
    split_f16(v.x,h[0],l[0]); split_f16(v.y,h[1],l[1]);
    split_f16(v.z,h[2],l[2]); split_f16(v.w,h[3],l[3]);
    __half2 h01; h01.x=h[0]; h01.y=h[1];
    __half2 h23; h23.x=h[2]; h23.y=h[3];
    __half2 l01; l01.x=l[0]; l01.y=l[1];
    __half2 l23; l23.x=l[2]; l23.y=l[3];
    ((__half2*)xh)[i*2]=h01; ((__half2*)xh)[i*2+1]=h23;
    ((__half2*)xl)[i*2]=l01; ((__half2*)xl)[i*2+1]=l23;
}

// W [K=256][N=256] -> Wt hi/lo [N][K]
__global__ __launch_bounds__(256) void convert_wt_kernel(
    const float* __restrict__ W, __half* __restrict__ Wth, __half* __restrict__ Wtl)
{
    int n = blockIdx.x, k = threadIdx.x;
    float v = W[k*D_ + n];
    __half h,l; split_f16(v,h,l);
    Wth[n*D_ + k]=h; Wtl[n*D_ + k]=l;
}

// ================= tensor-core projection ==================================
// A: X hi/lo [128 rows]; B: Wt hi/lo [256 rows]; stage = 30720 el = 61440 B;
// 3 stages. MODE 0=Q(f32+hi/lo+tanh hi/lo), 1=K(K16,tK16), 2=V(transposed Vt16)
#define PJ_STAGE_B 61440

__device__ __forceinline__ void pj_load_chunk(
    const __half* const* Am, const __half* const* Bm, uint32_t stage_b, int kc, int tid)
{
    #pragma unroll
    for (int t=0;t<6;t++) {
        int i = tid + t*512;                   // 0..3071
        const __half* src; uint32_t dst;
        if (i < 1024) {
            int m = i >> 9, rem = i & 511, row = rem >> 2, c8 = rem & 3;
            src = Am[m] + (size_t)row*D_ + kc + c8*8;
            dst = stage_b + (uint32_t)(m*5120 + row*40 + c8*8)*2u;
        } else {
            int j = i - 1024;                  // 0..2047
            int m = j >> 10, rem = j & 1023, row = rem >> 2, c8 = rem & 3;
            src = Bm[m] + (size_t)row*D_ + kc + c8*8;
            dst = stage_b + (uint32_t)(10240 + m*10240 + row*40 + c8*8)*2u;
        }
        CP_ASYNC16(dst, src);
    }
}

template<int MODE>
__global__ __launch_bounds__(512,1) void proj_mma_kernel(
    const __half* __restrict__ Xh, const __half* __restrict__ Xl,
    const __half* __restrict__ Wth, const __half* __restrict__ Wtl,
    const float* __restrict__ bias,
    float* __restrict__ Qf,
    __half* __restrict__ O1, __half* __restrict__ O2,
    __half* __restrict__ O3, __half* __restrict__ O4)
{
    extern __shared__ __align__(16) bf16 sm[];
    const uint32_t smb = smem_u32(sm);
    const int tid = threadIdx.x;
    const int warp = tid >> 5, lane = tid & 31;
    const int wm = warp >> 3, wn = warp & 7;      // 2 x 8
    const int g = lane >> 2, t4 = lane & 3;
    const int m3 = lane >> 3, rr = lane & 7;
    const int aRowOff = ((m3 & 1) << 3) + rr, aColOff = (m3 >> 1) << 3;
    const int bRowOff = ((m3 >> 1) << 3) + rr, bColOff = (m3 & 1) << 3;
    const int q0 = blockIdx.x * 128;

    const __half* Am[2] = { Xh + (size_t)q0*D_, Xl + (size_t)q0*D_ };
    const __half* Bm[2] = { Wth, Wtl };

    float acc[4][4][4] = {};

    pj_load_chunk(Am, Bm, smb, 0, tid);  CP_COMMIT();
    pj_load_chunk(Am, Bm, smb + PJ_STAGE_B, 32, tid);  CP_COMMIT();

    for (int ch = 0; ch < 8; ch++) {
        uint32_t sbase = smb + (uint32_t)(ch % 3) * PJ_STAGE_B;
        CP_WAIT1();
        __syncthreads();
        if (ch + 2 < 8)
            pj_load_chunk(Am, Bm, smb + (uint32_t)((ch+2) % 3) * PJ_STAGE_B, (ch+2)*32, tid);
        CP_COMMIT();
        #pragma unroll
        for (int ks = 0; ks < 2; ks++) {
            const int kb0 = ks*16;
            unsigned bF[2][4][2];
            #pragma unroll
            for (int mat = 0; mat < 2; mat++)
                #pragma unroll
                for (int p = 0; p < 2; p++) {
                    int N0 = wn*32 + p*16;
                    uint32_t addr = sbase + (uint32_t)(10240 + mat*10240 + (N0 + bRowOff)*40 + kb0 + bColOff)*2u;
                    unsigned r[4]; ldsm_x4(addr, r);
                    bF[mat][2*p  ][0]=r[0]; bF[mat][2*p  ][1]=r[1];
                    bF[mat][2*p+1][0]=r[2]; bF[mat][2*p+1][1]=r[3];
                }
            #pragma unroll
            for (int mt = 0; mt < 4; mt++) {
                int R = wm*64 + mt*16;
                unsigned a0[4], a1[4];
                uint32_t abase = sbase + (uint32_t)((R + aRowOff)*40 + kb0 + aColOff)*2u;
                ldsm_x4(abase,          a0);   // Xhi
                ldsm_x4(abase + 10240u, a1);   // Xlo
                #pragma unroll
                for (int nt=0; nt<4; nt++) {
                    mma16816h(acc[mt][nt], a0, bF[0][nt]);
                    mma16816h(acc[mt][nt], a0, bF[1][nt]);
                    mma16816h(acc[mt][nt], a1, bF[0][nt]);
                }
            }
        }
    }
    // add bias once
    #pragma unroll
    for (int mt=0; mt<4; mt++)
        #pragma unroll
        for (int nt=0; nt<4; nt++) {
            int c = wn*32 + nt*8 + 2*t4;
            float b0 = bias[c], b1 = bias[c+1];
            acc[mt][nt][0]+=b0; acc[mt][nt][1]+=b1;
            acc[mt][nt][2]+=b0; acc[mt][nt][3]+=b1;
        }
    __syncthreads();   // done reading pipeline smem

    if (MODE == 2) {
        // transpose through smem for coalesced Vt writes
        __half* Vs = (__half*)sm;              // [256 cols][136 rows pad]
        #pragma unroll
        for (int mt=0; mt<4; mt++)
            #pragma unroll
            for (int nt=0; nt<4; nt++) {
                int rl = wm*64 + mt*16 + g;
                int c  = wn*32 + nt*8 + 2*t4;
                Vs[(c  )*136 + rl    ] = __float2half_rn(acc[mt][nt][0]);
                Vs[(c+1)*136 + rl    ] = __float2half_rn(acc[mt][nt][1]);
                Vs[(c  )*136 + rl + 8] = __float2half_rn(acc[mt][nt][2]);
                Vs[(c+1)*136 + rl + 8] = __float2half_rn(acc[mt][nt][3]);
            }
        __syncthreads();
        int b = q0 >> 12, s0 = q0 & 4095;
        for (int i = tid; i < 256*16; i += 512) {
            int c = i >> 4, seg = i & 15;
            uint4 v = *(uint4*)(Vs + c*136 + seg*8);
            *(uint4*)(O1 + ((size_t)b*D_ + c)*NSEQ + s0 + seg*8) = v;
        }
        return;
    }

    // ---- fp16 streams, coalesced via smem staging [128][264] ----
    __half* Hs = (__half*)sm;
    const int nStreams = (MODE == 0) ? 4 : 2;
    #pragma unroll
    for (int st = 0; st < 4; st++) {
        if (st >= nStreams) break;
        #pragma unroll
        for (int mt=0; mt<4; mt++)
            #pragma unroll
            for (int nt=0; nt<4; nt++) {
                int rl = wm*64 + mt*16 + g;
                int c  = wn*32 + nt*8 + 2*t4;
                float v0=acc[mt][nt][0], v1=acc[mt][nt][1];
                float v2=acc[mt][nt][2], v3=acc[mt][nt][3];
                __half2 p0, p1;
                if (MODE == 0) {
                    if (st == 0) {         // Qhi
                        __half h,l; split_f16(v0,h,l); p0.x=h;
                        split_f16(v1,h,l); p0.y=h;
                        split_f16(v2,h,l); p1.x=h;
                        split_f16(v3,h,l); p1.y=h;
                    } else if (st == 1) {  // Qlo
                        __half h,l; split_f16(v0,h,l); p0.x=l;
                        split_f16(v1,h,l); p0.y=l;
                        split_f16(v2,h,l); p1.x=l;
                        split_f16(v3,h,l); p1.y=l;
                    } else if (st == 2) {  // tQh
                        __half h,l; split_f16(tanhf(v0),h,l); p0.x=h;
                        split_f16(tanhf(v1),h,l); p0.y=h;
                        split_f16(tanhf(v2),h,l); p1.x=h;
                        split_f16(tanhf(v3),h,l); p1.y=h;
                    } else {               // tQl
                        __half h,l; split_f16(tanhf(v0),h,l); p0.x=l;
                        split_f16(tanhf(v1),h,l); p0.y=l;
                        split_f16(tanhf(v2),h,l); p1.x=l;
                        split_f16(tanhf(v3),h,l); p1.y=l;
                    }
                } else {
                    if (st == 0) {         // K16
                        p0 = __floats2half2_rn(v0, v1);
                        p1 = __floats2half2_rn(v2, v3);
                    } else {               // tK16
                        p0 = __floats2half2_rn(tanhf(v0), tanhf(v1));
                        p1 = __floats2half2_rn(tanhf(v2), tanhf(v3));
                    }
                }
                *(__half2*)(Hs + (rl  )*264 + c) = p0;
                *(__half2*)(Hs + (rl+8)*264 + c) = p1;
            }
        __syncthreads();
        __half* Og = (st==0) ? O1 : (st==1) ? O2 : (st==2) ? O3 : O4;
        for (int i = tid; i < 128*32; i += 512) {
            int r = i >> 5, seg = i & 31;
            uint4 v = *(uint4*)(Hs + r*264 + seg*8);
            *(uint4*)(Og + (size_t)(q0+r)*D_ + seg*8) = v;
        }
        __syncthreads();
    }

    if (MODE == 0) {
        // f32 Q in two 128-col halves via smem [128][132]
        float* Fs = (float*)sm;
        #pragma unroll
        for (int h = 0; h < 2; h++) {
            if ((wn >> 2) == h) {
                #pragma unroll
                for (int mt=0; mt<4; mt++)
                    #pragma unroll
                    for (int nt=0; nt<4; nt++) {
                        int rl = wm*64 + mt*16 + g;
                        int c  = wn*32 + nt*8 + 2*t4 - h*128;
                        float2 u0 = { acc[mt][nt][0], acc[mt][nt][1] };
                        float2 u1 = { acc[mt][nt][2], acc[mt][nt][3] };
                        *(float2*)(Fs + (rl  )*132 + c) = u0;
                        *(float2*)(Fs + (rl+8)*132 + c) = u1;
                    }
            }
            __syncthreads();
            for (int i = tid; i < 128*32; i += 512) {
                int r = i >> 5, seg = i & 31;
                float4 v = *(float4*)(Fs + r*132 + seg*4);
                *(float4*)(Qf + (size_t)(q0+r)*D_ + h*128 + seg*4) = v;
            }
            __syncthreads();
        }
    }
}

// ====== dual-GEMM scores: 6 fp16 mats, asym QK + asym tanh =================
#define SC_STAGE_B  61440

__device__ __forceinline__ void sc_load_chunk(
    const __half* const* P, uint32_t stage_b, int kc, int tid)
{
    #pragma unroll
    for (int t=0;t<6;t++) {
        int i = tid + t*512;                    // 0..3071
        int m = i >> 9, rem = i & 511, row = rem >> 2, c8 = rem & 3;
        const __half* src = P[m] + (size_t)row*D_ + kc + c8*8;
        uint32_t dst = stage_b + (uint32_t)(m*5120 + row*40 + c8*8)*2u;
        CP_ASYNC16(dst, src);
    }
}

__global__ __launch_bounds__(512,1) void scores_mma_kernel(
    const __half* __restrict__ Qhi16, const __half* __restrict__ Qlo16,
    const __half* __restrict__ tQh16, const __half* __restrict__ tQl16,
    const __half* __restrict__ K16, const __half* __restrict__ tK16,
    float* __restrict__ attn)
{
    extern __shared__ __align__(16) bf16 sm[];
    const uint32_t smb = smem_u32(sm);
    const int tid = threadIdx.x;
    const int warp = tid >> 5, lane = tid & 31;
    const int wm = warp >> 2, wn = warp & 3;
    const int g = lane >> 2, t4 = lane & 3;
    const int m3 = lane >> 3, rr = lane & 7;
    const int aRowOff = ((m3 & 1) << 3) + rr, aColOff = (m3 >> 1) << 3;
    const int bRowOff = ((m3 >> 1) << 3) + rr, bColOff = (m3 & 1) << 3;
    const int bz = blockIdx.z;
    const int q0 = blockIdx.y * 128, c0 = blockIdx.x * 128;

    const __half* P[6] = {
        Qhi16 + ((size_t)bz*NSEQ + q0)*D_,
        Qlo16 + ((size_t)bz*NSEQ + q0)*D_,
        tQh16 + ((size_t)bz*NSEQ + q0)*D_,
        tQl16 + ((size_t)bz*NSEQ + q0)*D_,
        K16   + ((size_t)bz*NSEQ + c0)*D_,
        tK16  + ((size_t)bz*NSEQ + c0)*D_ };

    float accQ[2][4][4] = {};
    float accT[2][4][4] = {};

    sc_load_chunk(P, smb, 0, tid);  CP_COMMIT();
    sc_load_chunk(P, smb + SC_STAGE_B, 32, tid);  CP_COMMIT();

    for (int ch = 0; ch < 8; ch++) {
        uint32_t sbase = smb + (uint32_t)(ch % 3) * SC_STAGE_B;
        CP_WAIT1();
        __syncthreads();
        if (ch + 2 < 8)
            sc_load_chunk(P, smb + (uint32_t)((ch+2) % 3) * SC_STAGE_B, (ch+2)*32, tid);
        CP_COMMIT();
        #pragma unroll
        for (int ks = 0; ks < 2; ks++) {
            const int kb0 = ks*16;
            unsigned bF[2][4][2];
            #pragma unroll
            for (int mb = 0; mb < 2; mb++)
                #pragma unroll
                for (int p = 0; p < 2; p++) {
                    int N0 = wn*32 + p*16;
                    uint32_t addr = sbase + (uint32_t)((4+mb)*5120 + (N0 + bRowOff)*40 + kb0 + bColOff)*2u;
                    unsigned r[4]; ldsm_x4(addr, r);
                    bF[mb][2*p  ][0]=r[0]; bF[mb][2*p  ][1]=r[1];
                    bF[mb][2*p+1][0]=r[2]; bF[mb][2*p+1][1]=r[3];
                }
            #pragma unroll
            for (int mt = 0; mt < 2; mt++) {
                int R = wm*32 + mt*16;
                unsigned a0[4], a1[4], a2[4], a3[4];
                uint32_t abase = sbase + (uint32_t)((R + aRowOff)*40 + kb0 + aColOff)*2u;
                ldsm_x4(abase,            a0);   // Qhi16
                ldsm_x4(abase + 10240u,   a1);   // Qlo16
                ldsm_x4(abase + 20480u,   a2);   // tQh16
                ldsm_x4(abase + 30720u,   a3);   // tQl16
                #pragma unroll
                for (int nt=0; nt<4; nt++) {
                    mma16816h(accQ[mt][nt], a0, bF[0][nt]);
                    mma16816h(accQ[mt][nt], a1, bF[0][nt]);
                    mma16816h(accT[mt][nt], a2, bF[1][nt]);
                    mma16816h(accT[mt][nt], a3, bF[1][nt]);
                }
            }
        }
    }

    float* ob = attn + (size_t)bz*NSEQ*NSEQ;
    #pragma unroll
    for (int mt=0; mt<2; mt++)
        #pragma unroll
        for (int nt=0; nt<4; nt++) {
            int r = q0 + wm*32 + mt*16 + g;
            int c = c0 + wn*32 + nt*8 + 2*t4;
            const float* aq = accQ[mt][nt];
            const float* at = accT[mt][nt];
            float2 v0 = { aq[0]*(at[0]+1.0f)*0.03125f, aq[1]*(at[1]+1.0f)*0.03125f };
            float2 v1 = { aq[2]*(at[2]+1.0f)*0.03125f, aq[3]*(at[3]+1.0f)*0.03125f };
            *(float2*)(ob + (size_t)r*NSEQ + c)     = v0;
            *(float2*)(ob + (size_t)(r+8)*NSEQ + c) = v1;
        }
}

// ========= Qhat = attn @ V — fp16 asym: P hi/lo fp16 × V fp16 ===============
#define AV_STAGE_B  40960
#define AV_NCHUNK  (NSEQ/32)

__device__ __forceinline__ void av_load_chunk(
    const __half* const* Am, const __half* Bm, uint32_t stage_b, int kc, int tid)
{
    #pragma unroll
    for (int t=0;t<4;t++) {
        int i = tid + t*512;                   // 0..2047
        const __half* src; uint32_t dst;
        if (i < 1024) {
            int m = i >> 9, rem = i & 511, row = rem >> 2, c8 = rem & 3;
            src = Am[m] + (size_t)row*NSEQ + kc + c8*8;
            dst = stage_b + (uint32_t)(m*5120 + row*40 + c8*8)*2u;
        } else {
            int j = i - 1024;                  // 0..1023
            int row = j >> 2, c8 = j & 3;      // 256 rows
            src = Bm + (size_t)row*NSEQ + kc + c8*8;
            dst = stage_b + (uint32_t)(10240 + row*40 + c8*8)*2u;
        }
        CP_ASYNC16(dst, src);
    }
}

__global__ __launch_bounds__(512,1) void av_mma_kernel(
    const __half* __restrict__ Phi16, const __half* __restrict__ Plo16,
    const __half* __restrict__ Vt16,
    float* __restrict__ Qh)
{
    extern __shared__ __align__(16) bf16 sm[];
    const uint32_t smb = smem_u32(sm);
    const int tid = threadIdx.x;
    const int warp = tid >> 5, lane = tid & 31;
    const int wm = warp >> 2, wn = warp & 3;
    const int g = lane >> 2, t4 = lane & 3;
    const int m3 = lane >> 3, rr = lane & 7;
    const int aRowOff = ((m3 & 1) << 3) + rr, aColOff = (m3 >> 1) << 3;
    const int bRowOff = ((m3 >> 1) << 3) + rr, bColOff = (m3 & 1) << 3;
    const int bz = blockIdx.z;
    const int q0 = blockIdx.x * 128;

    const __half* Am[2] = { Phi16 + ((size_t)bz*NSEQ + q0)*NSEQ,
                            Plo16 + ((size_t)bz*NSEQ + q0)*NSEQ };
    const __half* Bm = Vt16 + (size_t)bz*D_*NSEQ;

    float acc[2][8][4] = {};

    av_load_chunk(Am, Bm, smb, 0, tid);  CP_COMMIT();
    av_load_chunk(Am, Bm, smb + AV_STAGE_B, 32, tid);  CP_COMMIT();

    for (int ch = 0; ch < AV_NCHUNK; ch++) {
        uint32_t sbase = smb + (uint32_t)(ch % 3) * AV_STAGE_B;
        CP_WAIT1();
        __syncthreads();
        if (ch + 2 < AV_NCHUNK)
            av_load_chunk(Am, Bm, smb + (uint32_t)((ch+2) % 3) * AV_STAGE_B, (ch+2)*32, tid);
        CP_COMMIT();
        #pragma unroll
        for (int ks = 0; ks < 2; ks++) {
            const int kb0 = ks*16;
            unsigned bF[8][2];
            #pragma unroll
            for (int p = 0; p < 4; p++) {
                int N0 = wn*64 + p*16;
                uint32_t addr = sbase + (uint32_t)(10240 + (N0 + bRowOff)*40 + kb0 + bColOff)*2u;
                unsigned r[4]; ldsm_x4(addr, r);
                bF[2*p  ][0]=r[0]; bF[2*p  ][1]=r[1];
                bF[2*p+1][0]=r[2]; bF[2*p+1][1]=r[3];
            }
            #pragma unroll
            for (int mt = 0; mt < 2; mt++) {
                int R = wm*32 + mt*16;
                unsigned a0[4], a1[4];
                uint32_t abase = sbase + (uint32_t)((R + aRowOff)*40 + kb0 + aColOff)*2u;
                ldsm_x4(abase,          a0);   // Phi16
                ldsm_x4(abase + 10240u, a1);   // Plo16
                #pragma unroll
                for (int nt=0; nt<8; nt++) {
                    mma16816h(acc[mt][nt], a0, bF[nt]);
                    mma16816h(acc[mt][nt], a1, bF[nt]);
                }
            }
        }
    }

    float* ob = Qh + ((size_t)bz*NSEQ + q0)*D_;
    #pragma unroll
    for (int mt=0; mt<2; mt++)
        #pragma unroll
        for (int nt=0; nt<8; nt++) {
            int r = wm*32 + mt*16 + g;
            int c = wn*64 + nt*8 + 2*t4;
            float2 v0 = { acc[mt][nt][0], acc[mt][nt][1] };
            float2 v1 = { acc[mt][nt][2], acc[mt][nt][3] };
            *(float2*)(ob + (size_t)r*D_ + c)     = v0;
            *(float2*)(ob + (size_t)(r+8)*D_ + c) = v1;
        }
}

// ======================= in-place row softmax (4096) + fp16 hi/lo ===========
__device__ __forceinline__ float blockMax256(float v) {
    __shared__ float sh[8];
    #pragma unroll
    for (int o=16;o>0;o>>=1) v = fmaxf(v, __shfl_xor_sync(0xffffffffu, v, o));
    if ((threadIdx.x & 31)==0) sh[threadIdx.x>>5] = v;
    __syncthreads();
    float m = sh[0];
    #pragma unroll
    for (int w=1;w<8;w++) m = fmaxf(m, sh[w]);
    __syncthreads();
    return m;
}
__device__ __forceinline__ float blockSum256(float v) {
    __shared__ float sh[8];
    #pragma unroll
    for (int o=16;o>0;o>>=1) v += __shfl_xor_sync(0xffffffffu, v, o);
    if ((threadIdx.x & 31)==0) sh[threadIdx.x>>5] = v;
    __syncthreads();
    float s = sh[0];
    #pragma unroll
    for (int w=1;w<8;w++) s += sh[w];
    __syncthreads();
    return s;
}
__global__ __launch_bounds__(256) void softmax_kernel(
    float* __restrict__ attn, __half* __restrict__ Phi, __half* __restrict__ Plo)
{
    size_t rb = (size_t)blockIdx.x * NSEQ;
    float4* p = (float4*)(attn + rb);
    int tid = threadIdx.x;
    float4 v[4];
    #pragma unroll
    for (int t=0;t<4;t++) v[t] = p[tid + 256*t];
    float m = -1e30f;
    #pragma unroll
    for (int t=0;t<4;t++)
        m = fmaxf(m, fmaxf(fmaxf(v[t].x, v[t].y), fmaxf(v[t].z, v[t].w)));
    m = blockMax256(m);
    float s = 0.f;
    #pragma unroll
    for (int t=0;t<4;t++) {
        v[t].x = __expf(v[t].x - m); v[t].y = __expf(v[t].y - m);
        v[t].z = __expf(v[t].z - m); v[t].w = __expf(v[t].w - m);
        s += v[t].x + v[t].y + v[t].z + v[t].w;
    }
    s = blockSum256(s);
    float inv = 1.0f / s;
    #pragma unroll
    for (int t=0;t<4;t++) {
        v[t].x *= inv; v[t].y *= inv; v[t].z *= inv; v[t].w *= inv;
        p[tid + 256*t] = v[t];
        int idx = (tid + 256*t)*4;
        float f[4] = {v[t].x, v[t].y, v[t].z, v[t].w};
        __half h[4], l[4];
        #pragma unroll
        for (int u=0;u<4;u++) split_f16(f[u], h[u], l[u]);
        __half2 h01; h01.x=h[0]; h01.y=h[1];
        __half2 h23; h23.x=h[2]; h23.y=h[3];
        __half2 l01; l01.x=l[0]; l01.y=l[1];
        __half2 l23; l23.x=l[2]; l23.y=l[3];
        __half2* hp = (__half2*)(Phi + rb + idx);
        __half2* lp = (__half2*)(Plo + rb + idx);
        hp[0]=h01; hp[1]=h23; lp[0]=l01; lp[1]=l23;
    }
}

// ===================== fused gate epilogue ==================================
__device__ __forceinline__ void blockSum2_128(float& a, float& b) {
    __shared__ float sh[8];
    #pragma unroll
    for (int o=16;o>0;o>>=1) {
        a += __shfl_xor_sync(0xffffffffu, a, o);
        b += __shfl_xor_sync(0xffffffffu, b, o);
    }
    if ((threadIdx.x & 31)==0) { sh[threadIdx.x>>5]=a; sh[4+(threadIdx.x>>5)]=b; }
    __syncthreads();
    a = sh[0]+sh[1]+sh[2]+sh[3];
    b = sh[4]+sh[5]+sh[6]+sh[7];
    __syncthreads();
}

__global__ __launch_bounds__(128) void epilogue_kernel(
    const float* __restrict__ Qg, const float* __restrict__ Qhg,
    const float* __restrict__ W1, const float* __restrict__ b1,
    const float* __restrict__ W2, const float* __restrict__ b2,
    const float* __restrict__ W3, const float* __restrict__ b3,
    const float* __restrict__ Wc, const float* __restrict__ bc,
    const float* __restrict__ Wf, const float* __restrict__ bf,
    const float* __restrict__ gg, const float* __restrict__ gb,
    const float* __restrict__ eg, const float* __restrict__ eb,
    float* __restrict__ out)
{
    __shared__ float Qs[EROWS][D_];
    __shared__ float Qh[EROWS][D_];
    __shared__ float ges[EROWS][NOUT];
    int j = threadIdx.x;
    size_t row0 = (size_t)blockIdx.x * EROWS;

    {
        const float4* s1 = (const float4*)(Qg  + row0*D_);
        const float4* s2 = (const float4*)(Qhg + row0*D_);
        float4* dQ = (float4*)&Qs[0][0];
        float4* dH = (float4*)&Qh[0][0];
        for (int t=j; t<EROWS*D_/4; t+=128) { dQ[t]=s1[t]; dH[t]=s2[t]; }
    }
    __syncthreads();

    float acc1[EROWS]={}, acc2[EROWS]={}, acc3[EROWS]={}, accF[EROWS]={};
    for (int c=0; c<D_; c+=4) {
        float w1v[4], w2v[4], w3v[4], wfv[4];
        #pragma unroll
        for (int u=0;u<4;u++) {
            w1v[u]=W1[(c+u)*NOUT+j]; w2v[u]=W2[(c+u)*NOUT+j];
            w3v[u]=W3[(c+u)*NOUT+j]; wfv[u]=Wf[(c+u)*NOUT+j];
        }
        #pragma unroll
        for (int r=0;r<EROWS;r++) {
            float4 q = *(const float4*)&Qs[r][c];
            float4 h = *(const float4*)&Qh[r][c];
            acc1[r] += q.x*w1v[0]+q.y*w1v[1]+q.z*w1v[2]+q.w*w1v[3];
            accF[r] += q.x*wfv[0]+q.y*wfv[1]+q.z*wfv[2]+q.w*wfv[3];
            acc2[r] += h.x*w2v[0]+h.y*w2v[1]+h.z*w2v[2]+h.w*w2v[3];
            acc3[r] += h.x*w3v[0]+h.y*w3v[1]+h.z*w3v[2]+h.w*w3v[3];
        }
    }

    float bb1=b1[j], bb2=b2[j], bb3=b3[j], bbf=bf[j], bbc=bc[j];
    float ggj=gg[j], gbj=gb[j], egj=eg[j], ebj=eb[j];

    #pragma unroll 1
    for (int r=0;r<EROWS;r++) {
        float gin = fmaxf(fmaxf(acc1[r]+bb1,0.f) + fmaxf(acc2[r]+bb2,0.f), 0.f);
        float ein = fmaxf(acc3[r]+bb3, 0.f);
        float s1 = gin, s2 = gin*gin;
        blockSum2_128(s1, s2);
        float mu  = s1*(1.0f/NOUT);
        float var = s2*(1.0f/NOUT) - mu*mu;
        float G = (gin-mu)*rsqrtf(var+EPS)*ggj + gbj;
        s1 = ein; s2 = ein*ein;
        blockSum2_128(s1, s2);
        mu  = s1*(1.0f/NOUT);
        var = s2*(1.0f/NOUT) - mu*mu;
        float E = (ein-mu)*rsqrtf(var+EPS)*egj + ebj;
        ges[r][j] = G*E;
        accF[r] = fmaxf(accF[r]+bbf, 0.f);
    }
    __syncthreads();

    float accC[EROWS]={};
    for (int k=0;k<NOUT;k++) {
        float wc = Wc[k*NOUT+j];
        #pragma unroll
        for (int r=0;r<EROWS;r++) accC[r] += ges[r][k]*wc;
    }
    #pragma unroll
    for (int r=0;r<EROWS;r++)
        out[(row0+r)*NOUT + j] = accF[r] + fmaxf(accC[r]+bbc, 0.f);
}

// ============================================================================
extern "C" void kernel_launch(void* const* d_in, const int* in_sizes, int n_in,
                              void* d_out, int out_size)
{
    const float* x1 = (const float*)d_in[0];
    const float* x2 = (const float*)d_in[1];
    const float* W_q=(const float*)d_in[2];  const float* b_q=(const float*)d_in[3];
    const float* W_k=(const float*)d_in[4];  const float* b_k=(const float*)d_in[5];
    const float* W_v=(const float*)d_in[6];  const float* b_v=(const float*)d_in[7];
    const float* W1 =(const float*)d_in[8];  const float* b1 =(const float*)d_in[9];
    const float* W2 =(const float*)d_in[10]; const float* b2 =(const float*)d_in[11];
    const float* W3 =(const float*)d_in[12]; const float* b3 =(const float*)d_in[13];
    const float* gg =(const float*)d_in[14]; const float* gb =(const float*)d_in[15];
    const float* eg =(const float*)d_in[16]; const float* eb =(const float*)d_in[17];
    const float* Wc =(const float*)d_in[18]; const float* bc =(const float*)d_in[19];
    const float* Wf =(const float*)d_in[20]; const float* bf =(const float*)d_in[21];

    float* out     = (float*)d_out;
    float* outMain = out;
    float* attn    = out + (size_t)MTOT*NOUT;

    float *Q,*Qh;
    __half *Qhi16,*Qlo16,*K16,*tQh16,*tQl16,*tK16,*Vt16,*Phi16,*Plo16;
    __half *x1h,*x1l,*x2h,*x2l,*wqh,*wql,*wkh,*wkl,*wvh,*wvl;
    cudaGetSymbolAddress((void**)&Q,     g_Q);
    cudaGetSymbolAddress((void**)&Qh,    g_Qh);
    cudaGetSymbolAddress((void**)&Qhi16, g_Qhi16); cudaGetSymbolAddress((void**)&Qlo16, g_Qlo16);
    cudaGetSymbolAddress((void**)&K16,   g_K16);
    cudaGetSymbolAddress((void**)&tQh16, g_tQh16); cudaGetSymbolAddress((void**)&tQl16, g_tQl16);
    cudaGetSymbolAddress((void**)&tK16,  g_tK16);
    cudaGetSymbolAddress((void**)&Vt16,  g_Vt16);
    cudaGetSymbolAddress((void**)&Phi16, g_Phi16); cudaGetSymbolAddress((void**)&Plo16, g_Plo16);
    cudaGetSymbolAddress((void**)&x1h, g_x1h); cudaGetSymbolAddress((void**)&x1l, g_x1l);
    cudaGetSymbolAddress((void**)&x2h, g_x2h); cudaGetSymbolAddress((void**)&x2l, g_x2l);
    cudaGetSymbolAddress((void**)&wqh, g_wqh); cudaGetSymbolAddress((void**)&wql, g_wql);
    cudaGetSymbolAddress((void**)&wkh, g_wkh); cudaGetSymbolAddress((void**)&wkl, g_wkl);
    cudaGetSymbolAddress((void**)&wvh, g_wvh); cudaGetSymbolAddress((void**)&wvl, g_wvl);

    cudaFuncSetAttribute(scores_mma_kernel, cudaFuncAttributeMaxDynamicSharedMemorySize, 3*SC_STAGE_B);
    cudaFuncSetAttribute(av_mma_kernel,     cudaFuncAttributeMaxDynamicSharedMemorySize, 3*AV_STAGE_B);
    cudaFuncSetAttribute(proj_mma_kernel<0>, cudaFuncAttributeMaxDynamicSharedMemorySize, 3*PJ_STAGE_B);
    cudaFuncSetAttribute(proj_mma_kernel<1>, cudaFuncAttributeMaxDynamicSharedMemorySize, 3*PJ_STAGE_B);
    cudaFuncSetAttribute(proj_mma_kernel<2>, cudaFuncAttributeMaxDynamicSharedMemorySize, 3*PJ_STAGE_B);

    convert_x_kernel<<<MTOT*D_/4/256, 256>>>(x2, x2h, x2l);
    convert_x_kernel<<<MTOT*D_/4/256, 256>>>(x1, x1h, x1l);
    convert_wt_kernel<<<D_, D_>>>(W_q, wqh, wql);
    convert_wt_kernel<<<D_, D_>>>(W_k, wkh, wkl);
    convert_wt_kernel<<<D_, D_>>>(W_v, wvh, wvl);

    proj_mma_kernel<0><<<MTOT/128, 512, 3*PJ_STAGE_B>>>(
        x2h, x2l, wqh, wql, b_q, Q, Qhi16, Qlo16, tQh16, tQl16);
    proj_mma_kernel<1><<<MTOT/128, 512, 3*PJ_STAGE_B>>>(
        x1h, x1l, wkh, wkl, b_k, nullptr, K16, tK16, nullptr, nullptr);
    proj_mma_kernel<2><<<MTOT/128, 512, 3*PJ_STAGE_B>>>(
        x1h, x1l, wvh, wvl, b_v, nullptr, Vt16, nullptr, nullptr, nullptr);

    scores_mma_kernel<<<dim3(NSEQ/128, NSEQ/128, B_), 512, 3*SC_STAGE_B>>>(
        Qhi16, Qlo16, tQh16, tQl16, K16, tK16, attn);

    softmax_kernel<<<MTOT, 256>>>(attn, Phi16, Plo16);

    av_mma_kernel<<<dim3(NSEQ/128, 1, B_), 512, 3*AV_STAGE_B>>>(Phi16, Plo16, Vt16, Qh);

    epilogue_kernel<<<MTOT/EROWS, 128>>>(Q, Qh, W1,b1, W2,b2, W3,b3,
                                         Wc,bc, Wf,bf, gg,gb, eg,eb, outMain);
}